// round 1
// baseline (speedup 1.0000x reference)
#include <cuda_runtime.h>
#include <math.h>

#define T_DIM 4096
#define C_DIM 2048
#define NF_DIM 2048
#define N3_DIM 6144

constexpr int BM = 128;
constexpr int BN = 128;

// Scratch (allocation-free rule: __device__ globals)
__device__ float g_qkv[(size_t)T_DIM * N3_DIM];  // 96 MB
__device__ float g_S[(size_t)T_DIM * T_DIM];     // 64 MB

__device__ __forceinline__ float f2tf32(float x) {
  unsigned u;
  asm("cvt.rna.tf32.f32 %0, %1;" : "=r"(u) : "f"(x));
  return __uint_as_float(u);
}

__device__ __forceinline__ void mma8(float c[4], const float a[4], const float b[2]) {
  asm volatile(
      "mma.sync.aligned.m16n8k8.row.col.f32.tf32.tf32.f32 "
      "{%0,%1,%2,%3}, {%4,%5,%6,%7}, {%8,%9}, {%0,%1,%2,%3};\n"
      : "+f"(c[0]), "+f"(c[1]), "+f"(c[2]), "+f"(c[3])
      : "r"(__float_as_uint(a[0])), "r"(__float_as_uint(a[1])),
        "r"(__float_as_uint(a[2])), "r"(__float_as_uint(a[3])),
        "r"(__float_as_uint(b[0])), "r"(__float_as_uint(b[1])));
}

// TRANSB: 0 -> B[K,N] row-major (NN). 1 -> B[N,K] row-major (NT, i.e. A@B^T).
// EPI: 0 none, 1 +bias[col], 2 *scale
// CSKIP: skip blocks entirely above the causal diagonal (GEMM2)
// CK:    bound K loop at r0+BM (GEMM3, causal columns of P)
// SPLIT: tf32x3 split-precision (GEMM1)
template <int TRANSB, int EPI, bool CSKIP, bool CK, bool SPLIT>
__global__ __launch_bounds__(256) void gemm_tf32(
    const float* __restrict__ A, const float* __restrict__ Bp,
    float* __restrict__ D, const float* __restrict__ bias, float scale,
    int K, int lda, int ldb, int ldd) {
  constexpr int BK = SPLIT ? 16 : 32;
  constexpr int KSTEPS = BK / 8;
  constexpr int NBUF = SPLIT ? 2 : 1;
  constexpr int BSTR = TRANSB ? (BK + 4) : (BN + 4);
  constexpr int BROW = TRANSB ? BN : BK;
  constexpr int BCOL = TRANSB ? BK : BN;

  __shared__ float As[NBUF][BM][BK + 4];
  __shared__ float Bs[NBUF][BROW * BSTR];

  const int r0 = blockIdx.y * BM;
  const int c0 = blockIdx.x * BN;
  if (CSKIP && c0 > r0 + BM - 1) return;  // fully masked block, never read

  int kend = K;
  if (CK) kend = min(K, r0 + BM);

  const int tid = threadIdx.x;
  const int lane = tid & 31;
  const int warp = tid >> 5;
  const int wm = (warp >> 2) * 64;  // 2 warps in M
  const int wn = (warp & 3) * 32;   // 4 warps in N

  float acc[4][4][4];
#pragma unroll
  for (int i = 0; i < 4; i++)
#pragma unroll
    for (int j = 0; j < 4; j++)
#pragma unroll
      for (int r = 0; r < 4; r++) acc[i][j][r] = 0.f;

  for (int kt = 0; kt < kend; kt += BK) {
    // ---- load A tile (BM x BK) ----
    constexpr int AIT = (BM * BK / 4) / 256;
    constexpr int AFR = BK / 4;
#pragma unroll
    for (int i = 0; i < AIT; i++) {
      int lin = tid + i * 256;
      int r = lin / AFR;
      int c4 = (lin % AFR) * 4;
      float4 v = *(const float4*)(A + (size_t)(r0 + r) * lda + kt + c4);
      float4 h;
      h.x = f2tf32(v.x); h.y = f2tf32(v.y); h.z = f2tf32(v.z); h.w = f2tf32(v.w);
      *(float4*)&As[0][r][c4] = h;
      if constexpr (SPLIT) {
        float4 l;
        l.x = f2tf32(v.x - h.x); l.y = f2tf32(v.y - h.y);
        l.z = f2tf32(v.z - h.z); l.w = f2tf32(v.w - h.w);
        *(float4*)&As[1][r][c4] = l;
      }
    }
    // ---- load B tile ----
    constexpr int BIT = (BROW * BCOL / 4) / 256;
    constexpr int BFR = BCOL / 4;
#pragma unroll
    for (int i = 0; i < BIT; i++) {
      int lin = tid + i * 256;
      int r = lin / BFR;
      int c4 = (lin % BFR) * 4;
      size_t goff = TRANSB ? ((size_t)(c0 + r) * ldb + kt + c4)
                           : ((size_t)(kt + r) * ldb + c0 + c4);
      float4 v = *(const float4*)(Bp + goff);
      float4 h;
      h.x = f2tf32(v.x); h.y = f2tf32(v.y); h.z = f2tf32(v.z); h.w = f2tf32(v.w);
      *(float4*)&Bs[0][r * BSTR + c4] = h;
      if constexpr (SPLIT) {
        float4 l;
        l.x = f2tf32(v.x - h.x); l.y = f2tf32(v.y - h.y);
        l.z = f2tf32(v.z - h.z); l.w = f2tf32(v.w - h.w);
        *(float4*)&Bs[1][r * BSTR + c4] = l;
      }
    }
    __syncthreads();

#pragma unroll
    for (int ks = 0; ks < KSTEPS; ks++) {
      const int kb = ks * 8;
      float ah[4][4], bh[4][2];
#pragma unroll
      for (int ma = 0; ma < 4; ma++) {
        int mr = wm + ma * 16 + (lane >> 2);
        int kc = kb + (lane & 3);
        ah[ma][0] = As[0][mr][kc];
        ah[ma][1] = As[0][mr + 8][kc];
        ah[ma][2] = As[0][mr][kc + 4];
        ah[ma][3] = As[0][mr + 8][kc + 4];
      }
#pragma unroll
      for (int na = 0; na < 4; na++) {
        int nc = wn + na * 8 + (lane >> 2);
        int kr = kb + (lane & 3);
        if constexpr (TRANSB) {
          bh[na][0] = Bs[0][nc * BSTR + kr];
          bh[na][1] = Bs[0][nc * BSTR + kr + 4];
        } else {
          bh[na][0] = Bs[0][kr * BSTR + nc];
          bh[na][1] = Bs[0][(kr + 4) * BSTR + nc];
        }
      }
#pragma unroll
      for (int ma = 0; ma < 4; ma++)
#pragma unroll
        for (int na = 0; na < 4; na++) mma8(acc[ma][na], ah[ma], bh[na]);

      if constexpr (SPLIT) {
        float al[4][4], bl[4][2];
#pragma unroll
        for (int ma = 0; ma < 4; ma++) {
          int mr = wm + ma * 16 + (lane >> 2);
          int kc = kb + (lane & 3);
          al[ma][0] = As[1][mr][kc];
          al[ma][1] = As[1][mr + 8][kc];
          al[ma][2] = As[1][mr][kc + 4];
          al[ma][3] = As[1][mr + 8][kc + 4];
        }
#pragma unroll
        for (int na = 0; na < 4; na++) {
          int nc = wn + na * 8 + (lane >> 2);
          int kr = kb + (lane & 3);
          bl[na][0] = Bs[1][nc * BSTR + kr];     // SPLIT only used with TRANSB=0
          bl[na][1] = Bs[1][nc * BSTR + kr + 4];
          if constexpr (!TRANSB) {
            bl[na][0] = Bs[1][kr * BSTR + nc];
            bl[na][1] = Bs[1][(kr + 4) * BSTR + nc];
          }
        }
#pragma unroll
        for (int ma = 0; ma < 4; ma++)
#pragma unroll
          for (int na = 0; na < 4; na++) {
            mma8(acc[ma][na], ah[ma], bl[na]);
            mma8(acc[ma][na], al[ma], bh[na]);
          }
      }
    }
    __syncthreads();
  }

  // ---- epilogue ----
#pragma unroll
  for (int ma = 0; ma < 4; ma++) {
#pragma unroll
    for (int na = 0; na < 4; na++) {
      int row = r0 + wm + ma * 16 + (lane >> 2);
      int col = c0 + wn + na * 8 + (lane & 3) * 2;
      float v0 = acc[ma][na][0], v1 = acc[ma][na][1];
      float v2 = acc[ma][na][2], v3 = acc[ma][na][3];
      if (EPI == 1) {
        float b0 = bias[col], b1 = bias[col + 1];
        v0 += b0; v1 += b1; v2 += b0; v3 += b1;
      }
      if (EPI == 2) { v0 *= scale; v1 *= scale; v2 *= scale; v3 *= scale; }
      *(float2*)(D + (size_t)row * ldd + col) = make_float2(v0, v1);
      *(float2*)(D + (size_t)(row + 8) * ldd + col) = make_float2(v2, v3);
    }
  }
}

// Row softmax over valid window [n_padd, row]; zeros everywhere else.
// Rows < n_padd are fully zeroed (matches reference's p-zeroing of pad rows).
__global__ void softmax_rows(float* __restrict__ S, const int* __restrict__ npad_p) {
  const int row = blockIdx.x;
  const int tid = threadIdx.x;
  const int npad = *npad_p;
  float* rp = S + (size_t)row * T_DIM;
  __shared__ float red[8];
  if (row < npad) {
    for (int c = tid; c < T_DIM; c += 256) rp[c] = 0.f;
    return;
  }
  const int lo = npad, hi = row;
  float m = -3.0e38f;
  for (int c = lo + tid; c <= hi; c += 256) m = fmaxf(m, rp[c]);
#pragma unroll
  for (int o = 16; o > 0; o >>= 1) m = fmaxf(m, __shfl_xor_sync(0xffffffffu, m, o));
  if ((tid & 31) == 0) red[tid >> 5] = m;
  __syncthreads();
  float bmax = red[0];
#pragma unroll
  for (int i = 1; i < 8; i++) bmax = fmaxf(bmax, red[i]);
  __syncthreads();
  float s = 0.f;
  for (int c = lo + tid; c <= hi; c += 256) {
    float e = __expf(rp[c] - bmax);
    rp[c] = e;
    s += e;
  }
#pragma unroll
  for (int o = 16; o > 0; o >>= 1) s += __shfl_xor_sync(0xffffffffu, s, o);
  if ((tid & 31) == 0) red[tid >> 5] = s;
  __syncthreads();
  float bsum = 0.f;
#pragma unroll
  for (int i = 0; i < 8; i++) bsum += red[i];
  const float inv = 1.0f / bsum;
  __syncthreads();
  for (int c = tid; c < T_DIM; c += 256) {
    float v = (c >= lo && c <= hi) ? rp[c] * inv : 0.f;
    rp[c] = v;
  }
}

extern "C" void kernel_launch(void* const* d_in, const int* in_sizes, int n_in,
                              void* d_out, int out_size) {
  const float* x = (const float*)d_in[0];
  const float* W = (const float*)d_in[1];
  const float* bias = (const float*)d_in[2];
  const int* n_padd = (const int*)d_in[3];
  float* y = (float*)d_out;

  float *qkv, *S;
  cudaGetSymbolAddress((void**)&qkv, g_qkv);
  cudaGetSymbolAddress((void**)&S, g_S);

  const float scale = 1.0f / sqrtf((float)NF_DIM);

  // GEMM1: qkv = x @ W + b   (tf32x3 split for near-fp32 q/k/v)
  gemm_tf32<0, 1, false, false, true>
      <<<dim3(N3_DIM / BN, T_DIM / BM), 256>>>(
          x, W, qkv, bias, 0.f, C_DIM, C_DIM, N3_DIM, N3_DIM);

  // GEMM2: S = (q @ k^T) * scale   (NT, causal block skip)
  gemm_tf32<1, 2, true, false, false>
      <<<dim3(T_DIM / BN, T_DIM / BM), 256>>>(
          qkv, qkv + NF_DIM, S, nullptr, scale, NF_DIM, N3_DIM, N3_DIM, T_DIM);

  // Row softmax with padding/causal mask -> P (in place in S)
  softmax_rows<<<T_DIM, 256>>>(S, n_padd);

  // GEMM3: y = P @ v   (NN, K bounded at r0+BM by causality)
  gemm_tf32<0, 0, false, true, false>
      <<<dim3(NF_DIM / BN, T_DIM / BM), 256>>>(
          S, qkv + 2 * NF_DIM, y, nullptr, 0.f, T_DIM, T_DIM, N3_DIM, NF_DIM);
}

// round 2
// speedup vs baseline: 1.0428x; 1.0428x over previous
#include <cuda_runtime.h>
#include <math.h>

#define T_DIM 4096
#define C_DIM 2048
#define NF_DIM 2048
#define N3_DIM 6144

constexpr int BM = 128;
constexpr int BN = 128;
constexpr int BK = 32;
constexpr int ASTR = BK + 4;  // 36 floats, 144B (16B-aligned rows)

// Scratch (allocation-free rule: __device__ globals)
__device__ float g_qkv[(size_t)T_DIM * N3_DIM];  // 96 MB
__device__ float g_S[(size_t)T_DIM * T_DIM];     // 64 MB

__device__ __forceinline__ float f2tf32(float x) {
  unsigned u;
  asm("cvt.rna.tf32.f32 %0, %1;" : "=r"(u) : "f"(x));
  return __uint_as_float(u);
}

__device__ __forceinline__ void mma8(float c[4], const float a[4], const float b[2]) {
  asm volatile(
      "mma.sync.aligned.m16n8k8.row.col.f32.tf32.tf32.f32 "
      "{%0,%1,%2,%3}, {%4,%5,%6,%7}, {%8,%9}, {%0,%1,%2,%3};\n"
      : "+f"(c[0]), "+f"(c[1]), "+f"(c[2]), "+f"(c[3])
      : "r"(__float_as_uint(a[0])), "r"(__float_as_uint(a[1])),
        "r"(__float_as_uint(a[2])), "r"(__float_as_uint(a[3])),
        "r"(__float_as_uint(b[0])), "r"(__float_as_uint(b[1])));
}

__device__ __forceinline__ void cpasync16(unsigned saddr, const void* g) {
  asm volatile("cp.async.cg.shared.global [%0], [%1], 16;\n" ::"r"(saddr), "l"(g));
}
__device__ __forceinline__ void cp_commit() {
  asm volatile("cp.async.commit_group;\n" ::);
}
template <int N>
__device__ __forceinline__ void cp_wait() {
  asm volatile("cp.async.wait_group %0;\n" ::"n"(N));
}

// TRANSB: 0 -> B[K,N] row-major (NN). 1 -> B[N,K] row-major (NT / A@B^T).
// EPI: 0 none, 1 +bias[col], 2 *scale
// CSKIP: skip blocks above causal diagonal (GEMM2)
// CK:    bound K loop at r0+BM (GEMM3)
// SPLIT: tf32x3 split-precision, consumer-side (GEMM1)
template <int TRANSB, int EPI, bool CSKIP, bool CK, bool SPLIT>
__global__ __launch_bounds__(256, SPLIT ? 1 : 2) void gemm_tf32(
    const float* __restrict__ A, const float* __restrict__ Bp,
    float* __restrict__ D, const float* __restrict__ bias, float scale,
    int K, int lda, int ldb, int ldd) {
  constexpr int BSTR = TRANSB ? (BK + 4) : (BN + 4);
  constexpr int BROW = TRANSB ? BN : BK;
  constexpr int ASZ = BM * ASTR;    // floats per A stage
  constexpr int BSZ = BROW * BSTR;  // floats per B stage

  extern __shared__ float smem[];
  float* Asm = smem;            // [2][ASZ]
  float* Bsm = smem + 2 * ASZ;  // [2][BSZ]
  const unsigned sA = (unsigned)__cvta_generic_to_shared(Asm);
  const unsigned sB = (unsigned)__cvta_generic_to_shared(Bsm);

  const int r0 = blockIdx.y * BM;
  const int c0 = blockIdx.x * BN;
  if (CSKIP && c0 > r0 + BM - 1) return;

  int kend = K;
  if (CK) kend = min(K, r0 + BM);
  const int nk = kend / BK;

  const int tid = threadIdx.x;
  const int lane = tid & 31;
  const int warp = tid >> 5;
  const int wm = (warp >> 2) * 64;
  const int wn = (warp & 3) * 32;

  // Precomputed load coords (4 float4 each for A and B)
  const int ar_ = tid >> 3;             // 0..31 step -> rows via +32*i
  const int ac4 = (tid & 7) * 4;        // col within BK
  // B coords depend on layout
  const int bnn_r = tid >> 5;           // NN: 0..7 (+8*i)
  const int bnn_c4 = (tid & 31) * 4;    // NN: col within BN
  const int bnt_r = tid >> 3;           // NT: 0..31 (+32*i)
  const int bnt_c4 = (tid & 7) * 4;     // NT: col within BK

  auto load_tile = [&](int st, int kt) {
#pragma unroll
    for (int i = 0; i < 4; i++) {
      int r = ar_ + i * 32;
      cpasync16(sA + (unsigned)(st * ASZ + r * ASTR + ac4) * 4,
                A + (size_t)(r0 + r) * lda + kt + ac4);
    }
#pragma unroll
    for (int i = 0; i < 4; i++) {
      if constexpr (TRANSB) {
        int r = bnt_r + i * 32;
        cpasync16(sB + (unsigned)(st * BSZ + r * BSTR + bnt_c4) * 4,
                  Bp + (size_t)(c0 + r) * ldb + kt + bnt_c4);
      } else {
        int r = bnn_r + i * 8;
        cpasync16(sB + (unsigned)(st * BSZ + r * BSTR + bnn_c4) * 4,
                  Bp + (size_t)(kt + r) * ldb + c0 + bnn_c4);
      }
    }
  };

  float acc[4][4][4];
#pragma unroll
  for (int i = 0; i < 4; i++)
#pragma unroll
    for (int j = 0; j < 4; j++)
#pragma unroll
      for (int r = 0; r < 4; r++) acc[i][j][r] = 0.f;

  load_tile(0, 0);
  cp_commit();

  for (int k = 0; k < nk; k++) {
    const int cur = k & 1;
    if (k + 1 < nk) {
      load_tile(cur ^ 1, (k + 1) * BK);
      cp_commit();
      cp_wait<1>();
    } else {
      cp_wait<0>();
    }
    __syncthreads();

    const float* Ab = Asm + cur * ASZ;
    const float* Bb = Bsm + cur * BSZ;

#pragma unroll
    for (int ks = 0; ks < 4; ks++) {
      const int kb = ks * 8;
      float ar[4][4], br[4][2];   // raw fp32 fragments
      float ah[4][4], bh[4][2];   // tf32 hi
#pragma unroll
      for (int ma = 0; ma < 4; ma++) {
        int mr = wm + ma * 16 + (lane >> 2);
        int kc = kb + (lane & 3);
        ar[ma][0] = Ab[mr * ASTR + kc];
        ar[ma][1] = Ab[(mr + 8) * ASTR + kc];
        ar[ma][2] = Ab[mr * ASTR + kc + 4];
        ar[ma][3] = Ab[(mr + 8) * ASTR + kc + 4];
#pragma unroll
        for (int t = 0; t < 4; t++) ah[ma][t] = f2tf32(ar[ma][t]);
      }
#pragma unroll
      for (int na = 0; na < 4; na++) {
        int nc = wn + na * 8 + (lane >> 2);
        int kr = kb + (lane & 3);
        if constexpr (TRANSB) {
          br[na][0] = Bb[nc * BSTR + kr];
          br[na][1] = Bb[nc * BSTR + kr + 4];
        } else {
          br[na][0] = Bb[kr * BSTR + nc];
          br[na][1] = Bb[(kr + 4) * BSTR + nc];
        }
        bh[na][0] = f2tf32(br[na][0]);
        bh[na][1] = f2tf32(br[na][1]);
      }
#pragma unroll
      for (int ma = 0; ma < 4; ma++)
#pragma unroll
        for (int na = 0; na < 4; na++) mma8(acc[ma][na], ah[ma], bh[na]);

      if constexpr (SPLIT) {
        // lo parts, in place over raw arrays (raw dead after this)
#pragma unroll
        for (int ma = 0; ma < 4; ma++)
#pragma unroll
          for (int t = 0; t < 4; t++) ar[ma][t] = f2tf32(ar[ma][t] - ah[ma][t]);
#pragma unroll
        for (int na = 0; na < 4; na++) {
          br[na][0] = f2tf32(br[na][0] - bh[na][0]);
          br[na][1] = f2tf32(br[na][1] - bh[na][1]);
        }
#pragma unroll
        for (int ma = 0; ma < 4; ma++)
#pragma unroll
          for (int na = 0; na < 4; na++) {
            mma8(acc[ma][na], ah[ma], br[na]);  // hi*lo
            mma8(acc[ma][na], ar[ma], bh[na]);  // lo*hi
          }
      }
    }
    __syncthreads();
  }

  // ---- epilogue ----
#pragma unroll
  for (int ma = 0; ma < 4; ma++) {
#pragma unroll
    for (int na = 0; na < 4; na++) {
      int row = r0 + wm + ma * 16 + (lane >> 2);
      int col = c0 + wn + na * 8 + (lane & 3) * 2;
      float v0 = acc[ma][na][0], v1 = acc[ma][na][1];
      float v2 = acc[ma][na][2], v3 = acc[ma][na][3];
      if (EPI == 1) {
        float b0 = bias[col], b1 = bias[col + 1];
        v0 += b0; v1 += b1; v2 += b0; v3 += b1;
      }
      if (EPI == 2) { v0 *= scale; v1 *= scale; v2 *= scale; v3 *= scale; }
      *(float2*)(D + (size_t)row * ldd + col) = make_float2(v0, v1);
      *(float2*)(D + (size_t)(row + 8) * ldd + col) = make_float2(v2, v3);
    }
  }
}

// Row softmax over valid window [n_padd, row]; zeros everywhere else.
__global__ void softmax_rows(float* __restrict__ S, const int* __restrict__ npad_p) {
  const int row = blockIdx.x;
  const int tid = threadIdx.x;
  const int npad = *npad_p;
  float* rp = S + (size_t)row * T_DIM;
  __shared__ float red[8];
  if (row < npad) {
    for (int c = tid; c < T_DIM; c += 256) rp[c] = 0.f;
    return;
  }
  const int lo = npad, hi = row;
  float m = -3.0e38f;
  for (int c = lo + tid; c <= hi; c += 256) m = fmaxf(m, rp[c]);
#pragma unroll
  for (int o = 16; o > 0; o >>= 1) m = fmaxf(m, __shfl_xor_sync(0xffffffffu, m, o));
  if ((tid & 31) == 0) red[tid >> 5] = m;
  __syncthreads();
  float bmax = red[0];
#pragma unroll
  for (int i = 1; i < 8; i++) bmax = fmaxf(bmax, red[i]);
  __syncthreads();
  float s = 0.f;
  for (int c = lo + tid; c <= hi; c += 256) {
    float e = __expf(rp[c] - bmax);
    rp[c] = e;
    s += e;
  }
#pragma unroll
  for (int o = 16; o > 0; o >>= 1) s += __shfl_xor_sync(0xffffffffu, s, o);
  if ((tid & 31) == 0) red[tid >> 5] = s;
  __syncthreads();
  float bsum = 0.f;
#pragma unroll
  for (int i = 0; i < 8; i++) bsum += red[i];
  const float inv = 1.0f / bsum;
  __syncthreads();
  for (int c = tid; c < T_DIM; c += 256) {
    float v = (c >= lo && c <= hi) ? rp[c] * inv : 0.f;
    rp[c] = v;
  }
}

extern "C" void kernel_launch(void* const* d_in, const int* in_sizes, int n_in,
                              void* d_out, int out_size) {
  const float* x = (const float*)d_in[0];
  const float* W = (const float*)d_in[1];
  const float* bias = (const float*)d_in[2];
  const int* n_padd = (const int*)d_in[3];
  float* y = (float*)d_out;

  float *qkv, *S;
  cudaGetSymbolAddress((void**)&qkv, g_qkv);
  cudaGetSymbolAddress((void**)&S, g_S);

  const float scale = 1.0f / sqrtf((float)NF_DIM);

  // dynamic smem sizes (2 stages, raw fp32)
  constexpr int SM_NN = (2 * BM * ASTR + 2 * BK * (BN + 4)) * 4;   // 70656
  constexpr int SM_NT = (2 * BM * ASTR + 2 * BN * (BK + 4)) * 4;   // 73728

  cudaFuncSetAttribute((const void*)gemm_tf32<0, 1, false, false, true>,
                       cudaFuncAttributeMaxDynamicSharedMemorySize, SM_NN);
  cudaFuncSetAttribute((const void*)gemm_tf32<1, 2, true, false, false>,
                       cudaFuncAttributeMaxDynamicSharedMemorySize, SM_NT);
  cudaFuncSetAttribute((const void*)gemm_tf32<0, 0, false, true, false>,
                       cudaFuncAttributeMaxDynamicSharedMemorySize, SM_NN);

  // GEMM1: qkv = x @ W + b   (tf32x3 split)
  gemm_tf32<0, 1, false, false, true>
      <<<dim3(N3_DIM / BN, T_DIM / BM), 256, SM_NN>>>(
          x, W, qkv, bias, 0.f, C_DIM, C_DIM, N3_DIM, N3_DIM);

  // GEMM2: S = (q @ k^T) * scale   (NT, causal block skip)
  gemm_tf32<1, 2, true, false, false>
      <<<dim3(T_DIM / BN, T_DIM / BM), 256, SM_NT>>>(
          qkv, qkv + NF_DIM, S, nullptr, scale, NF_DIM, N3_DIM, N3_DIM, T_DIM);

  // Softmax with padding/causal mask (in place)
  softmax_rows<<<T_DIM, 256>>>(S, n_padd);

  // GEMM3: y = P @ v   (NN, causal K bound)
  gemm_tf32<0, 0, false, true, false>
      <<<dim3(NF_DIM / BN, T_DIM / BM), 256, SM_NN>>>(
          S, qkv + 2 * NF_DIM, y, nullptr, 0.f, T_DIM, T_DIM, N3_DIM, NF_DIM);
}

// round 3
// speedup vs baseline: 1.0535x; 1.0103x over previous
#include <cuda_runtime.h>
#include <math.h>

#define T_DIM 4096
#define C_DIM 2048
#define NF_DIM 2048
#define N3_DIM 6144

constexpr int BM = 128;
constexpr int BN = 128;

// Scratch (allocation-free rule: __device__ globals)
__device__ float g_qkv[(size_t)T_DIM * N3_DIM];  // 96 MB (tf32-rounded)
__device__ float g_S[(size_t)T_DIM * T_DIM];     // 64 MB
__device__ float g_xh[(size_t)T_DIM * C_DIM];    // 33.5 MB
__device__ float g_xl[(size_t)T_DIM * C_DIM];
__device__ float g_wh[(size_t)C_DIM * N3_DIM];   // 50.3 MB
__device__ float g_wl[(size_t)C_DIM * N3_DIM];

__device__ __forceinline__ float f2tf32(float x) {
  unsigned u;
  asm("cvt.rna.tf32.f32 %0, %1;" : "=r"(u) : "f"(x));
  return __uint_as_float(u);
}

__device__ __forceinline__ void mma8(float c[4], const float a[4], const float b[2]) {
  asm volatile(
      "mma.sync.aligned.m16n8k8.row.col.f32.tf32.tf32.f32 "
      "{%0,%1,%2,%3}, {%4,%5,%6,%7}, {%8,%9}, {%0,%1,%2,%3};\n"
      : "+f"(c[0]), "+f"(c[1]), "+f"(c[2]), "+f"(c[3])
      : "r"(__float_as_uint(a[0])), "r"(__float_as_uint(a[1])),
        "r"(__float_as_uint(a[2])), "r"(__float_as_uint(a[3])),
        "r"(__float_as_uint(b[0])), "r"(__float_as_uint(b[1])));
}

__device__ __forceinline__ void cpasync16(unsigned saddr, const void* g) {
  asm volatile("cp.async.cg.shared.global [%0], [%1], 16;\n" ::"r"(saddr), "l"(g));
}
__device__ __forceinline__ void cp_commit() {
  asm volatile("cp.async.commit_group;\n" ::);
}
template <int N>
__device__ __forceinline__ void cp_wait() {
  asm volatile("cp.async.wait_group %0;\n" ::"n"(N));
}

// hi/lo tf32 split prep: hi = rna(v), lo = rna(v - hi)
__global__ __launch_bounds__(256) void split_prep(const float* __restrict__ in,
                                                  float* __restrict__ hi,
                                                  float* __restrict__ lo, int n4) {
  int i = blockIdx.x * 256 + threadIdx.x;
  if (i >= n4) return;
  float4 v = ((const float4*)in)[i];
  float4 h, l;
  h.x = f2tf32(v.x); h.y = f2tf32(v.y); h.z = f2tf32(v.z); h.w = f2tf32(v.w);
  l.x = f2tf32(v.x - h.x); l.y = f2tf32(v.y - h.y);
  l.z = f2tf32(v.z - h.z); l.w = f2tf32(v.w - h.w);
  ((float4*)hi)[i] = h;
  ((float4*)lo)[i] = l;
}

// TRANSB: 0 -> B[K,N] row-major (NN). 1 -> B[N,K] row-major (NT / A@B^T).
// EPI: 0 none, 1 +bias then tf32-round, 2 *scale
// CSKIP: skip blocks above causal diagonal (GEMM2)
// CK:    bound K loop at r0+BM (GEMM3)
// SPLIT: hi/lo operand pairs (A2/B2), 3 MMAs per element (GEMM1)
template <int TRANSB, int EPI, bool CSKIP, bool CK, bool SPLIT>
__global__ __launch_bounds__(256, 2) void gemm_tf32(
    const float* __restrict__ A, const float* __restrict__ Bp,
    const float* __restrict__ A2, const float* __restrict__ B2,
    float* __restrict__ D, const float* __restrict__ bias, float scale,
    int K, int lda, int ldb, int ldd) {
  constexpr int BK = SPLIT ? 16 : 32;
  constexpr int KSTEPS = BK / 8;
  constexpr int ASTR = BK + 4;
  constexpr int BSTR = TRANSB ? (BK + 4) : (BN + 4);
  constexpr int BROW = TRANSB ? BN : BK;
  constexpr int ASZ = BM * ASTR;
  constexpr int BSZ = BROW * BSTR;

  extern __shared__ float smem[];
  float* Ah = smem;                                  // [2][ASZ]
  float* Al = SPLIT ? (smem + 2 * ASZ) : nullptr;    // [2][ASZ]
  float* Bh = smem + (SPLIT ? 4 : 2) * ASZ;          // [2][BSZ]
  float* Bl = SPLIT ? (Bh + 2 * BSZ) : nullptr;      // [2][BSZ]
  const unsigned sAh = (unsigned)__cvta_generic_to_shared(Ah);
  const unsigned sAl = SPLIT ? (unsigned)__cvta_generic_to_shared(Al) : 0u;
  const unsigned sBh = (unsigned)__cvta_generic_to_shared(Bh);
  const unsigned sBl = SPLIT ? (unsigned)__cvta_generic_to_shared(Bl) : 0u;

  const int r0 = blockIdx.y * BM;
  const int c0 = blockIdx.x * BN;
  if (CSKIP && c0 > r0 + BM - 1) return;

  int kend = K;
  if (CK) kend = min(K, r0 + BM);
  const int nk = kend / BK;

  const int tid = threadIdx.x;
  const int lane = tid & 31;
  const int warp = tid >> 5;
  const int wm = (warp >> 2) * 64;
  const int wn = (warp & 3) * 32;

  auto load_tile = [&](int st, int kt) {
    if constexpr (SPLIT) {
      // A: 128x16 -> 512 float4, 2/thread; B: 16x128 -> 512 float4, 2/thread
      const int ar = tid >> 2, ac4 = (tid & 3) * 4;
      const int br = tid >> 5, bc4 = (tid & 31) * 4;
#pragma unroll
      for (int i = 0; i < 2; i++) {
        int r = ar + i * 64;
        size_t go = (size_t)(r0 + r) * lda + kt + ac4;
        unsigned so = (unsigned)(st * ASZ + r * ASTR + ac4) * 4;
        cpasync16(sAh + so, A + go);
        cpasync16(sAl + so, A2 + go);
      }
#pragma unroll
      for (int i = 0; i < 2; i++) {
        int r = br + i * 8;
        size_t go = (size_t)(kt + r) * ldb + c0 + bc4;
        unsigned so = (unsigned)(st * BSZ + r * BSTR + bc4) * 4;
        cpasync16(sBh + so, Bp + go);
        cpasync16(sBl + so, B2 + go);
      }
    } else {
      const int ar = tid >> 3, ac4 = (tid & 7) * 4;
#pragma unroll
      for (int i = 0; i < 4; i++) {
        int r = ar + i * 32;
        cpasync16(sAh + (unsigned)(st * ASZ + r * ASTR + ac4) * 4,
                  A + (size_t)(r0 + r) * lda + kt + ac4);
      }
#pragma unroll
      for (int i = 0; i < 4; i++) {
        if constexpr (TRANSB) {
          int r = (tid >> 3) + i * 32;
          int c4 = (tid & 7) * 4;
          cpasync16(sBh + (unsigned)(st * BSZ + r * BSTR + c4) * 4,
                    Bp + (size_t)(c0 + r) * ldb + kt + c4);
        } else {
          int r = (tid >> 5) + i * 8;
          int c4 = (tid & 31) * 4;
          cpasync16(sBh + (unsigned)(st * BSZ + r * BSTR + c4) * 4,
                    Bp + (size_t)(kt + r) * ldb + c0 + c4);
        }
      }
    }
  };

  float acc[4][4][4];
#pragma unroll
  for (int i = 0; i < 4; i++)
#pragma unroll
    for (int j = 0; j < 4; j++)
#pragma unroll
      for (int r = 0; r < 4; r++) acc[i][j][r] = 0.f;

  load_tile(0, 0);
  cp_commit();

  for (int k = 0; k < nk; k++) {
    const int cur = k & 1;
    if (k + 1 < nk) {
      load_tile(cur ^ 1, (k + 1) * BK);
      cp_commit();
      cp_wait<1>();
    } else {
      cp_wait<0>();
    }
    __syncthreads();

    const float* Ab = Ah + cur * ASZ;
    const float* Bb = Bh + cur * BSZ;

#pragma unroll
    for (int ks = 0; ks < KSTEPS; ks++) {
      const int kb = ks * 8;
      float ah[4][4], bh[4][2];
#pragma unroll
      for (int ma = 0; ma < 4; ma++) {
        int mr = wm + ma * 16 + (lane >> 2);
        int kc = kb + (lane & 3);
        ah[ma][0] = Ab[mr * ASTR + kc];
        ah[ma][1] = Ab[(mr + 8) * ASTR + kc];
        ah[ma][2] = Ab[mr * ASTR + kc + 4];
        ah[ma][3] = Ab[(mr + 8) * ASTR + kc + 4];
      }
#pragma unroll
      for (int na = 0; na < 4; na++) {
        int nc = wn + na * 8 + (lane >> 2);
        int kr = kb + (lane & 3);
        if constexpr (TRANSB) {
          bh[na][0] = Bb[nc * BSTR + kr];
          bh[na][1] = Bb[nc * BSTR + kr + 4];
        } else {
          bh[na][0] = Bb[kr * BSTR + nc];
          bh[na][1] = Bb[(kr + 4) * BSTR + nc];
        }
      }
#pragma unroll
      for (int ma = 0; ma < 4; ma++)
#pragma unroll
        for (int na = 0; na < 4; na++) mma8(acc[ma][na], ah[ma], bh[na]);

      if constexpr (SPLIT) {
        const float* Ab2 = Al + cur * ASZ;
        const float* Bb2 = Bl + cur * BSZ;
        // hi * lo
        float bl[4][2];
#pragma unroll
        for (int na = 0; na < 4; na++) {
          int nc = wn + na * 8 + (lane >> 2);
          int kr = kb + (lane & 3);
          bl[na][0] = Bb2[kr * BSTR + nc];
          bl[na][1] = Bb2[(kr + 4) * BSTR + nc];
        }
#pragma unroll
        for (int ma = 0; ma < 4; ma++)
#pragma unroll
          for (int na = 0; na < 4; na++) mma8(acc[ma][na], ah[ma], bl[na]);
        // lo * hi
        float al[4][4];
#pragma unroll
        for (int ma = 0; ma < 4; ma++) {
          int mr = wm + ma * 16 + (lane >> 2);
          int kc = kb + (lane & 3);
          al[ma][0] = Ab2[mr * ASTR + kc];
          al[ma][1] = Ab2[(mr + 8) * ASTR + kc];
          al[ma][2] = Ab2[mr * ASTR + kc + 4];
          al[ma][3] = Ab2[(mr + 8) * ASTR + kc + 4];
        }
#pragma unroll
        for (int ma = 0; ma < 4; ma++)
#pragma unroll
          for (int na = 0; na < 4; na++) mma8(acc[ma][na], al[ma], bh[na]);
      }
    }
    __syncthreads();
  }

  // ---- epilogue ----
#pragma unroll
  for (int ma = 0; ma < 4; ma++) {
#pragma unroll
    for (int na = 0; na < 4; na++) {
      int row = r0 + wm + ma * 16 + (lane >> 2);
      int col = c0 + wn + na * 8 + (lane & 3) * 2;
      float v0 = acc[ma][na][0], v1 = acc[ma][na][1];
      float v2 = acc[ma][na][2], v3 = acc[ma][na][3];
      if (EPI == 1) {
        float b0 = bias[col], b1 = bias[col + 1];
        v0 = f2tf32(v0 + b0); v1 = f2tf32(v1 + b1);
        v2 = f2tf32(v2 + b0); v3 = f2tf32(v3 + b1);
      }
      if (EPI == 2) { v0 *= scale; v1 *= scale; v2 *= scale; v3 *= scale; }
      *(float2*)(D + (size_t)row * ldd + col) = make_float2(v0, v1);
      *(float2*)(D + (size_t)(row + 8) * ldd + col) = make_float2(v2, v3);
    }
  }
}

// Row softmax over valid window [n_padd, row]; zeros elsewhere.
// Writes tf32-rounded P so GEMM3 needs no conversion (bit-identical to
// rounding at GEMM3's load).
__global__ void softmax_rows(float* __restrict__ S, const int* __restrict__ npad_p) {
  const int row = blockIdx.x;
  const int tid = threadIdx.x;
  const int npad = *npad_p;
  float* rp = S + (size_t)row * T_DIM;
  __shared__ float red[8];
  if (row < npad) {
    for (int c = tid; c < T_DIM; c += 256) rp[c] = 0.f;
    return;
  }
  const int lo = npad, hi = row;
  float m = -3.0e38f;
  for (int c = lo + tid; c <= hi; c += 256) m = fmaxf(m, rp[c]);
#pragma unroll
  for (int o = 16; o > 0; o >>= 1) m = fmaxf(m, __shfl_xor_sync(0xffffffffu, m, o));
  if ((tid & 31) == 0) red[tid >> 5] = m;
  __syncthreads();
  float bmax = red[0];
#pragma unroll
  for (int i = 1; i < 8; i++) bmax = fmaxf(bmax, red[i]);
  __syncthreads();
  float s = 0.f;
  for (int c = lo + tid; c <= hi; c += 256) {
    float e = __expf(rp[c] - bmax);
    rp[c] = e;
    s += e;
  }
#pragma unroll
  for (int o = 16; o > 0; o >>= 1) s += __shfl_xor_sync(0xffffffffu, s, o);
  if ((tid & 31) == 0) red[tid >> 5] = s;
  __syncthreads();
  float bsum = 0.f;
#pragma unroll
  for (int i = 0; i < 8; i++) bsum += red[i];
  const float inv = 1.0f / bsum;
  __syncthreads();
  for (int c = tid; c < T_DIM; c += 256) {
    float v = (c >= lo && c <= hi) ? f2tf32(rp[c] * inv) : 0.f;
    rp[c] = v;
  }
}

extern "C" void kernel_launch(void* const* d_in, const int* in_sizes, int n_in,
                              void* d_out, int out_size) {
  const float* x = (const float*)d_in[0];
  const float* W = (const float*)d_in[1];
  const float* bias = (const float*)d_in[2];
  const int* n_padd = (const int*)d_in[3];
  float* y = (float*)d_out;

  float *qkv, *S, *xh, *xl, *wh, *wl;
  cudaGetSymbolAddress((void**)&qkv, g_qkv);
  cudaGetSymbolAddress((void**)&S, g_S);
  cudaGetSymbolAddress((void**)&xh, g_xh);
  cudaGetSymbolAddress((void**)&xl, g_xl);
  cudaGetSymbolAddress((void**)&wh, g_wh);
  cudaGetSymbolAddress((void**)&wl, g_wl);

  const float scale = 1.0f / sqrtf((float)NF_DIM);

  // smem: 2 stages
  constexpr int SM_G1 = (4 * BM * 20 + 4 * 16 * (BN + 4)) * 4;      // 74752
  constexpr int SM_NT = (2 * BM * 36 + 2 * BN * 36) * 4;            // 73728
  constexpr int SM_NN = (2 * BM * 36 + 2 * 32 * (BN + 4)) * 4;      // 70656

  cudaFuncSetAttribute((const void*)gemm_tf32<0, 1, false, false, true>,
                       cudaFuncAttributeMaxDynamicSharedMemorySize, SM_G1);
  cudaFuncSetAttribute((const void*)gemm_tf32<1, 2, true, false, false>,
                       cudaFuncAttributeMaxDynamicSharedMemorySize, SM_NT);
  cudaFuncSetAttribute((const void*)gemm_tf32<0, 0, false, true, false>,
                       cudaFuncAttributeMaxDynamicSharedMemorySize, SM_NN);

  // Prep: hi/lo split of x and W
  split_prep<<<(T_DIM * C_DIM / 4 + 255) / 256, 256>>>(x, xh, xl, T_DIM * C_DIM / 4);
  split_prep<<<(C_DIM * N3_DIM / 4 + 255) / 256, 256>>>(W, wh, wl, C_DIM * N3_DIM / 4);

  // GEMM1: qkv = x @ W + b  (tf32x3 via prepped hi/lo; writes tf32-rounded)
  gemm_tf32<0, 1, false, false, true>
      <<<dim3(N3_DIM / BN, T_DIM / BM), 256, SM_G1>>>(
          xh, wh, xl, wl, qkv, bias, 0.f, C_DIM, C_DIM, N3_DIM, N3_DIM);

  // GEMM2: S = (q @ k^T) * scale  (NT, causal block skip; inputs pre-rounded)
  gemm_tf32<1, 2, true, false, false>
      <<<dim3(T_DIM / BN, T_DIM / BM), 256, SM_NT>>>(
          qkv, qkv + NF_DIM, nullptr, nullptr, S, nullptr, scale,
          NF_DIM, N3_DIM, N3_DIM, T_DIM);

  // Softmax (in place; writes tf32-rounded P)
  softmax_rows<<<T_DIM, 256>>>(S, n_padd);

  // GEMM3: y = P @ v  (NN, causal K bound; inputs pre-rounded)
  gemm_tf32<0, 0, false, true, false>
      <<<dim3(NF_DIM / BN, T_DIM / BM), 256, SM_NN>>>(
          S, qkv + 2 * NF_DIM, nullptr, nullptr, y, nullptr, 0.f,
          T_DIM, T_DIM, N3_DIM, NF_DIM);
}

// round 5
// speedup vs baseline: 1.9774x; 1.8770x over previous
#include <cuda_runtime.h>
#include <cuda_fp16.h>
#include <cuda_bf16.h>
#include <math.h>
#include <cstdint>

#define T_DIM 4096
#define C_DIM 2048
#define NF_DIM 2048
#define N3_DIM 6144

constexpr int BM = 128, BN = 256, BK = 32;  // BK in half-elements (64B rows)
constexpr int NST = 3;                       // pipeline stages

// Scratch (allocation-free rule: __device__ globals)
__device__ __half g_qkv[(size_t)T_DIM * N3_DIM];       // fp16 qkv (48 MB)
__device__ float g_S[(size_t)T_DIM * T_DIM];           // att logits (64 MB)
__device__ __half g_P[(size_t)T_DIM * T_DIM];          // P * 2^14 (32 MB)
__device__ __nv_bfloat16 g_xh[(size_t)T_DIM * C_DIM];
__device__ __nv_bfloat16 g_xl[(size_t)T_DIM * C_DIM];
__device__ __nv_bfloat16 g_wth[(size_t)N3_DIM * C_DIM];  // W^T hi
__device__ __nv_bfloat16 g_wtl[(size_t)N3_DIM * C_DIM];  // W^T lo
__device__ __half g_vt[(size_t)NF_DIM * T_DIM];          // v^T fp16

__device__ __forceinline__ void cpasync16(unsigned s, const void* g) {
  asm volatile("cp.async.cg.shared.global [%0], [%1], 16;\n" ::"r"(s), "l"(g));
}
__device__ __forceinline__ void cp_commit() { asm volatile("cp.async.commit_group;\n" ::); }
template <int N>
__device__ __forceinline__ void cp_wait() {
  asm volatile("cp.async.wait_group %0;\n" ::"n"(N));
}
__device__ __forceinline__ uint32_t lds32(unsigned a) {
  uint32_t v;
  asm volatile("ld.shared.b32 %0, [%1];" : "=r"(v) : "r"(a));
  return v;
}

template <bool BF>
__device__ __forceinline__ void mma16(float (&c)[4], const uint32_t (&a)[4],
                                      const uint32_t (&b)[2]) {
  if constexpr (BF)
    asm volatile(
        "mma.sync.aligned.m16n8k16.row.col.f32.bf16.bf16.f32 "
        "{%0,%1,%2,%3}, {%4,%5,%6,%7}, {%8,%9}, {%0,%1,%2,%3};\n"
        : "+f"(c[0]), "+f"(c[1]), "+f"(c[2]), "+f"(c[3])
        : "r"(a[0]), "r"(a[1]), "r"(a[2]), "r"(a[3]), "r"(b[0]), "r"(b[1]));
  else
    asm volatile(
        "mma.sync.aligned.m16n8k16.row.col.f32.f16.f16.f32 "
        "{%0,%1,%2,%3}, {%4,%5,%6,%7}, {%8,%9}, {%0,%1,%2,%3};\n"
        : "+f"(c[0]), "+f"(c[1]), "+f"(c[2]), "+f"(c[3])
        : "r"(a[0]), "r"(a[1]), "r"(a[2]), "r"(a[3]), "r"(b[0]), "r"(b[1]));
}

// ---------------------------------------------------------------------------
// 16-bit NT GEMM: D[M,N] = A[M,K] @ B[N,K]^T   (fp16 or bf16 inputs, fp32 acc)
// CTA 128x256, 8 warps of 64x64, BK=32 halves, XOR-swizzled 64B smem rows.
// EPI: 0 -> float out * scale ; 1 -> half out + bias
// CSKIP: causal block skip (GEMM2)   CK: causal K bound (GEMM3)
// SPLIT: x3 split with hi/lo operand pairs A2/B2 (GEMM1, bf16)
// ---------------------------------------------------------------------------
template <bool BF, int EPI, bool CSKIP, bool CK, bool SPLIT>
__global__ __launch_bounds__(256) void gemm_h(
    const uint16_t* __restrict__ A, const uint16_t* __restrict__ B,
    const uint16_t* __restrict__ A2, const uint16_t* __restrict__ B2,
    void* __restrict__ Dv, const float* __restrict__ bias, float scale,
    int K, int lda, int ldb, int ldd) {
  constexpr int ATB = BM * 64;   // 8 KB per A operand tile
  constexpr int BTB = BN * 64;   // 16 KB per B operand tile
  constexpr int STG = (SPLIT ? 2 : 1) * (ATB + BTB);
  extern __shared__ __align__(16) char smem[];

  const int r0 = blockIdx.y * BM, c0 = blockIdx.x * BN;
  if (CSKIP && c0 > r0 + BM - 1) return;
  const int kend = CK ? min(K, r0 + BM) : K;
  const int nk = kend / BK;

  const int tid = threadIdx.x, lane = tid & 31, warp = tid >> 5;
  const int wm = (warp & 1) * 64, wn = (warp >> 1) * 64;
  const unsigned sbase = (unsigned)__cvta_generic_to_shared(smem);

  auto sw_off = [](int r, int c) {
    return (unsigned)(r * 64 + ((c ^ ((r >> 1) & 3)) << 4));
  };
  auto load_A = [&](unsigned dst, const uint16_t* g, int kt) {
#pragma unroll
    for (int i = 0; i < 2; i++) {
      int id = tid + i * 256, r = id >> 2, c = id & 3;
      cpasync16(dst + sw_off(r, c), g + (size_t)(r0 + r) * lda + kt + c * 8);
    }
  };
  auto load_B = [&](unsigned dst, const uint16_t* g, int kt) {
#pragma unroll
    for (int i = 0; i < 4; i++) {
      int id = tid + i * 256, r = id >> 2, c = id & 3;
      cpasync16(dst + sw_off(r, c), g + (size_t)(c0 + r) * ldb + kt + c * 8);
    }
  };
  auto load_stage = [&](int s, int kt) {
    unsigned b = sbase + s * STG;
    load_A(b, A, kt);
    if constexpr (SPLIT) load_A(b + ATB, A2, kt);
    load_B(b + (SPLIT ? 2 : 1) * ATB, B, kt);
    if constexpr (SPLIT) load_B(b + 2 * ATB + BTB, B2, kt);
    cp_commit();
  };

  float acc[4][8][4];
#pragma unroll
  for (int i = 0; i < 4; i++)
#pragma unroll
    for (int j = 0; j < 8; j++)
#pragma unroll
      for (int r = 0; r < 4; r++) acc[i][j][r] = 0.f;

#pragma unroll
  for (int s = 0; s < NST - 1; s++) load_stage(s, s * BK);

  const int q = lane >> 2, t2 = lane & 3;
  const int sw = lane >> 3;          // == (r>>1)&3 for all this thread's rows
  const unsigned fb = (unsigned)(t2 * 4);

  for (int k = 0; k < nk; k++) {
    cp_wait<NST - 2>();
    __syncthreads();
    if (k + NST - 1 < nk) load_stage((k + NST - 1) % NST, (k + NST - 1) * BK);
    else cp_commit();  // keep group count consistent

    const unsigned sb = sbase + (unsigned)((k % NST) * STG);
    const unsigned sA = sb, sA2 = sb + ATB;
    const unsigned sB = sb + (SPLIT ? 2 : 1) * ATB, sB2 = sb + 2 * ATB + BTB;

#pragma unroll
    for (int ks = 0; ks < 2; ks++) {
      const int kc0 = ks * 2;
      const unsigned ch0 = (unsigned)((kc0 ^ sw) << 4);
      const unsigned ch1 = (unsigned)(((kc0 + 1) ^ sw) << 4);

      uint32_t ah[4][4], bh[8][2];
#pragma unroll
      for (int ma = 0; ma < 4; ma++) {
        unsigned rb0 = sA + (unsigned)((wm + ma * 16 + q) * 64) + fb;
        unsigned rb1 = rb0 + 8 * 64;
        ah[ma][0] = lds32(rb0 + ch0);
        ah[ma][1] = lds32(rb1 + ch0);
        ah[ma][2] = lds32(rb0 + ch1);
        ah[ma][3] = lds32(rb1 + ch1);
      }
#pragma unroll
      for (int na = 0; na < 8; na++) {
        unsigned nb = sB + (unsigned)((wn + na * 8 + q) * 64) + fb;
        bh[na][0] = lds32(nb + ch0);
        bh[na][1] = lds32(nb + ch1);
      }
#pragma unroll
      for (int ma = 0; ma < 4; ma++)
#pragma unroll
        for (int na = 0; na < 8; na++) mma16<BF>(acc[ma][na], ah[ma], bh[na]);

      if constexpr (SPLIT) {
        uint32_t bl[8][2];
#pragma unroll
        for (int na = 0; na < 8; na++) {
          unsigned nb = sB2 + (unsigned)((wn + na * 8 + q) * 64) + fb;
          bl[na][0] = lds32(nb + ch0);
          bl[na][1] = lds32(nb + ch1);
        }
#pragma unroll
        for (int ma = 0; ma < 4; ma++)
#pragma unroll
          for (int na = 0; na < 8; na++) mma16<BF>(acc[ma][na], ah[ma], bl[na]);
        uint32_t al[4][4];
#pragma unroll
        for (int ma = 0; ma < 4; ma++) {
          unsigned rb0 = sA2 + (unsigned)((wm + ma * 16 + q) * 64) + fb;
          unsigned rb1 = rb0 + 8 * 64;
          al[ma][0] = lds32(rb0 + ch0);
          al[ma][1] = lds32(rb1 + ch0);
          al[ma][2] = lds32(rb0 + ch1);
          al[ma][3] = lds32(rb1 + ch1);
        }
#pragma unroll
        for (int ma = 0; ma < 4; ma++)
#pragma unroll
          for (int na = 0; na < 8; na++) mma16<BF>(acc[ma][na], al[ma], bh[na]);
      }
    }
  }

  // ---- epilogue ----
#pragma unroll
  for (int ma = 0; ma < 4; ma++) {
#pragma unroll
    for (int na = 0; na < 8; na++) {
      const int row = r0 + wm + ma * 16 + q;
      const int col = c0 + wn + na * 8 + t2 * 2;
      float v0 = acc[ma][na][0], v1 = acc[ma][na][1];
      float v2 = acc[ma][na][2], v3 = acc[ma][na][3];
      if constexpr (EPI == 1) {
        __half* D = (__half*)Dv;
        float b0 = bias[col], b1 = bias[col + 1];
        *(__half2*)(D + (size_t)row * ldd + col) = __floats2half2_rn(v0 + b0, v1 + b1);
        *(__half2*)(D + (size_t)(row + 8) * ldd + col) = __floats2half2_rn(v2 + b0, v3 + b1);
      } else {
        float* D = (float*)Dv;
        *(float2*)(D + (size_t)row * ldd + col) = make_float2(v0 * scale, v1 * scale);
        *(float2*)(D + (size_t)(row + 8) * ldd + col) = make_float2(v2 * scale, v3 * scale);
      }
    }
  }
}

// ---------------------------------------------------------------------------
// Prep kernels
// ---------------------------------------------------------------------------
__global__ __launch_bounds__(256) void split_x(const float* __restrict__ in,
                                               __nv_bfloat16* __restrict__ hi,
                                               __nv_bfloat16* __restrict__ lo, int n4) {
  int i = blockIdx.x * 256 + threadIdx.x;
  if (i >= n4) return;
  float4 v = ((const float4*)in)[i];
  __nv_bfloat16 h0 = __float2bfloat16_rn(v.x), h1 = __float2bfloat16_rn(v.y);
  __nv_bfloat16 h2 = __float2bfloat16_rn(v.z), h3 = __float2bfloat16_rn(v.w);
  __nv_bfloat162* hp = (__nv_bfloat162*)(hi + (size_t)i * 4);
  hp[0] = __nv_bfloat162(h0, h1);
  hp[1] = __nv_bfloat162(h2, h3);
  __nv_bfloat162* lp = (__nv_bfloat162*)(lo + (size_t)i * 4);
  lp[0] = __nv_bfloat162(__float2bfloat16_rn(v.x - __bfloat162float(h0)),
                         __float2bfloat16_rn(v.y - __bfloat162float(h1)));
  lp[1] = __nv_bfloat162(__float2bfloat16_rn(v.z - __bfloat162float(h2)),
                         __float2bfloat16_rn(v.w - __bfloat162float(h3)));
}

// W [C, N3] float -> W^T [N3, C] bf16 hi/lo
__global__ __launch_bounds__(256) void transpose_w(const float* __restrict__ W,
                                                   __nv_bfloat16* __restrict__ oh,
                                                   __nv_bfloat16* __restrict__ ol) {
  __shared__ float t[32][33];
  const int bx = blockIdx.x * 32, by = blockIdx.y * 32;
  const int tx = threadIdx.x & 31, ty = threadIdx.x >> 5;
#pragma unroll
  for (int i = 0; i < 4; i++)
    t[ty + i * 8][tx] = W[(size_t)(by + ty + i * 8) * N3_DIM + bx + tx];
  __syncthreads();
#pragma unroll
  for (int i = 0; i < 4; i++) {
    float v = t[tx][ty + i * 8];
    size_t o = (size_t)(bx + ty + i * 8) * C_DIM + by + tx;
    __nv_bfloat16 h = __float2bfloat16_rn(v);
    oh[o] = h;
    ol[o] = __float2bfloat16_rn(v - __bfloat162float(h));
  }
}

// v (qkv cols [4096,6144)) half -> v^T [NF, T] half
__global__ __launch_bounds__(256) void transpose_v(const __half* __restrict__ qkv,
                                                   __half* __restrict__ vt) {
  __shared__ __half t[32][34];
  const int bx = blockIdx.x * 32, by = blockIdx.y * 32;
  const int tx = threadIdx.x & 31, ty = threadIdx.x >> 5;
#pragma unroll
  for (int i = 0; i < 4; i++)
    t[ty + i * 8][tx] = qkv[(size_t)(by + ty + i * 8) * N3_DIM + 2 * NF_DIM + bx + tx];
  __syncthreads();
#pragma unroll
  for (int i = 0; i < 4; i++)
    vt[(size_t)(bx + ty + i * 8) * T_DIM + by + tx] = t[tx][ty + i * 8];
}

// ---------------------------------------------------------------------------
// Row softmax over [n_padd, row]; writes P*2^14 as fp16; zeros elsewhere.
// ---------------------------------------------------------------------------
__global__ void softmax_rows(const float* __restrict__ S, __half* __restrict__ P,
                             const int* __restrict__ npad_p) {
  const int row = blockIdx.x;
  const int tid = threadIdx.x;
  const int npad = *npad_p;
  const float* rp = S + (size_t)row * T_DIM;
  __half* pp = P + (size_t)row * T_DIM;
  __shared__ float red[8];
  if (row < npad) {
    for (int c = tid; c < T_DIM; c += 256) pp[c] = __float2half(0.f);
    return;
  }
  const int lo = npad, hi = row;
  float m = -3.0e38f;
  for (int c = lo + tid; c <= hi; c += 256) m = fmaxf(m, rp[c]);
#pragma unroll
  for (int o = 16; o > 0; o >>= 1) m = fmaxf(m, __shfl_xor_sync(0xffffffffu, m, o));
  if ((tid & 31) == 0) red[tid >> 5] = m;
  __syncthreads();
  float bmax = red[0];
#pragma unroll
  for (int i = 1; i < 8; i++) bmax = fmaxf(bmax, red[i]);
  __syncthreads();
  float s = 0.f;
  for (int c = lo + tid; c <= hi; c += 256) s += __expf(rp[c] - bmax);
#pragma unroll
  for (int o = 16; o > 0; o >>= 1) s += __shfl_xor_sync(0xffffffffu, s, o);
  if ((tid & 31) == 0) red[tid >> 5] = s;
  __syncthreads();
  float bsum = 0.f;
#pragma unroll
  for (int i = 0; i < 8; i++) bsum += red[i];
  const float inv = 16384.0f / bsum;  // P pre-scaled by 2^14 (exact pow2)
  for (int c = tid; c < T_DIM; c += 256) {
    float v = (c >= lo && c <= hi) ? __expf(rp[c] - bmax) * inv : 0.f;
    pp[c] = __float2half_rn(v);
  }
}

extern "C" void kernel_launch(void* const* d_in, const int* in_sizes, int n_in,
                              void* d_out, int out_size) {
  const float* x = (const float*)d_in[0];
  const float* W = (const float*)d_in[1];
  const float* bias = (const float*)d_in[2];
  const int* n_padd = (const int*)d_in[3];
  float* y = (float*)d_out;

  __half *qkv, *P, *vt;
  float* S;
  __nv_bfloat16 *xh, *xl, *wth, *wtl;
  cudaGetSymbolAddress((void**)&qkv, g_qkv);
  cudaGetSymbolAddress((void**)&S, g_S);
  cudaGetSymbolAddress((void**)&P, g_P);
  cudaGetSymbolAddress((void**)&xh, g_xh);
  cudaGetSymbolAddress((void**)&xl, g_xl);
  cudaGetSymbolAddress((void**)&wth, g_wth);
  cudaGetSymbolAddress((void**)&wtl, g_wtl);
  cudaGetSymbolAddress((void**)&vt, g_vt);

  const float scale = 1.0f / sqrtf((float)NF_DIM);

  constexpr int SM_SINGLE = NST * (BM * 64 + BN * 64);      // 73728
  constexpr int SM_SPLIT = NST * 2 * (BM * 64 + BN * 64);   // 147456

  cudaFuncSetAttribute((const void*)gemm_h<true, 1, false, false, true>,
                       cudaFuncAttributeMaxDynamicSharedMemorySize, SM_SPLIT);
  cudaFuncSetAttribute((const void*)gemm_h<false, 0, true, false, false>,
                       cudaFuncAttributeMaxDynamicSharedMemorySize, SM_SINGLE);
  cudaFuncSetAttribute((const void*)gemm_h<false, 0, false, true, false>,
                       cudaFuncAttributeMaxDynamicSharedMemorySize, SM_SINGLE);

  // Prep: x -> bf16 hi/lo ; W -> W^T bf16 hi/lo
  split_x<<<(T_DIM * C_DIM / 4 + 255) / 256, 256>>>(x, xh, xl, T_DIM * C_DIM / 4);
  transpose_w<<<dim3(N3_DIM / 32, C_DIM / 32), 256>>>(W, wth, wtl);

  // GEMM1: qkv = x @ W + b   (bf16x3 split; writes fp16)
  gemm_h<true, 1, false, false, true>
      <<<dim3(N3_DIM / BN, T_DIM / BM), 256, SM_SPLIT>>>(
          (const uint16_t*)xh, (const uint16_t*)wth, (const uint16_t*)xl,
          (const uint16_t*)wtl, qkv, bias, 0.f, C_DIM, C_DIM, C_DIM, N3_DIM);

  // v^T
  transpose_v<<<dim3(NF_DIM / 32, T_DIM / 32), 256>>>(qkv, vt);

  // GEMM2: S = (q @ k^T) * scale   (fp16, causal block skip)
  gemm_h<false, 0, true, false, false>
      <<<dim3(T_DIM / BN, T_DIM / BM), 256, SM_SINGLE>>>(
          (const uint16_t*)qkv, (const uint16_t*)(qkv + NF_DIM), nullptr, nullptr,
          S, nullptr, scale, NF_DIM, N3_DIM, N3_DIM, T_DIM);

  // Softmax -> P (fp16, *2^14)
  softmax_rows<<<T_DIM, 256>>>(S, P, n_padd);

  // GEMM3: y = P @ v * 2^-14   (fp16, causal K bound)
  gemm_h<false, 0, false, true, false>
      <<<dim3(NF_DIM / BN, T_DIM / BM), 256, SM_SINGLE>>>(
          (const uint16_t*)P, (const uint16_t*)vt, nullptr, nullptr,
          y, nullptr, 6.103515625e-05f, T_DIM, T_DIM, T_DIM, NF_DIM);
}

// round 6
// speedup vs baseline: 2.5100x; 1.2694x over previous
#include <cuda_runtime.h>
#include <cuda_fp16.h>
#include <math.h>
#include <cstdint>

#define T_DIM 4096
#define C_DIM 2048
#define NF_DIM 2048
#define N3_DIM 6144

constexpr int BM = 128, BN = 256, BK = 32;  // BK in half-elements (64B rows)
constexpr int NST = 3;                       // pipeline stages
constexpr int NTHR = 512;                    // 16 warps: 2(M) x 8(N) of 64x32

// Scratch (allocation-free rule: __device__ globals)
__device__ __half g_qkv[(size_t)T_DIM * N3_DIM];   // fp16 qkv (48 MB)
__device__ float g_S[(size_t)T_DIM * T_DIM];       // att logits (64 MB)
__device__ __half g_P[(size_t)T_DIM * T_DIM];      // P (fp16, scaled)
__device__ __half g_xh[(size_t)T_DIM * C_DIM];
__device__ __half g_xl[(size_t)T_DIM * C_DIM];
__device__ __half g_wth[(size_t)N3_DIM * C_DIM];   // W^T hi
__device__ __half g_wtl[(size_t)N3_DIM * C_DIM];   // W^T lo (unused in GEMM; kept for split)
__device__ __half g_vt[(size_t)NF_DIM * T_DIM];    // v^T fp16

__device__ __forceinline__ void cpasync16(unsigned s, const void* g) {
  asm volatile("cp.async.cg.shared.global [%0], [%1], 16;\n" ::"r"(s), "l"(g));
}
__device__ __forceinline__ void cp_commit() { asm volatile("cp.async.commit_group;\n" ::); }
template <int N>
__device__ __forceinline__ void cp_wait() {
  asm volatile("cp.async.wait_group %0;\n" ::"n"(N));
}
__device__ __forceinline__ uint32_t lds32(unsigned a) {
  uint32_t v;
  asm volatile("ld.shared.b32 %0, [%1];" : "=r"(v) : "r"(a));
  return v;
}
__device__ __forceinline__ void mma16(float (&c)[4], const uint32_t (&a)[4],
                                      const uint32_t (&b)[2]) {
  asm volatile(
      "mma.sync.aligned.m16n8k16.row.col.f32.f16.f16.f32 "
      "{%0,%1,%2,%3}, {%4,%5,%6,%7}, {%8,%9}, {%0,%1,%2,%3};\n"
      : "+f"(c[0]), "+f"(c[1]), "+f"(c[2]), "+f"(c[3])
      : "r"(a[0]), "r"(a[1]), "r"(a[2]), "r"(a[3]), "r"(b[0]), "r"(b[1]));
}

// ---------------------------------------------------------------------------
// fp16 NT GEMM: D[M,N] = A[M,K] @ B[N,K]^T   (fp32 accum)
// CTA 128x256, 16 warps of 64x32, BK=32 halves, XOR-swizzled 64B smem rows.
// EPI: 0 -> float out * scale ; 1 -> half out + bias
// CSKIP: causal block skip (GEMM2)   CK: causal K bound (GEMM3)
// SPLIT: fp16x2: acc += A_hi@B + A_lo@B (A2 = A_lo)
// ---------------------------------------------------------------------------
template <int EPI, bool CSKIP, bool CK, bool SPLIT>
__global__ __launch_bounds__(NTHR, 1) void gemm_h(
    const uint16_t* __restrict__ A, const uint16_t* __restrict__ B,
    const uint16_t* __restrict__ A2,
    void* __restrict__ Dv, const float* __restrict__ bias, float scale,
    int K, int lda, int ldb, int ldd) {
  constexpr int ATB = BM * 64;   // 8 KB per A operand tile
  constexpr int BTB = BN * 64;   // 16 KB per B tile
  constexpr int STG = (SPLIT ? 2 : 1) * ATB + BTB;
  extern __shared__ __align__(16) char smem[];

  const int r0 = blockIdx.y * BM, c0 = blockIdx.x * BN;
  if (CSKIP && c0 > r0 + BM - 1) return;
  const int kend = CK ? min(K, r0 + BM) : K;
  const int nk = kend / BK;

  const int tid = threadIdx.x, lane = tid & 31, warp = tid >> 5;
  const int wm = (warp >> 3) * 64, wn = (warp & 7) * 32;
  const unsigned sbase = (unsigned)__cvta_generic_to_shared(smem);

  auto sw_off = [](int r, int c) {
    return (unsigned)(r * 64 + ((c ^ ((r >> 1) & 3)) << 4));
  };
  auto load_A = [&](unsigned dst, const uint16_t* g, int kt) {
    int r = tid >> 2, c = tid & 3;  // 128 rows x 4 chunks = 512
    cpasync16(dst + sw_off(r, c), g + (size_t)(r0 + r) * lda + kt + c * 8);
  };
  auto load_B = [&](unsigned dst, const uint16_t* g, int kt) {
#pragma unroll
    for (int i = 0; i < 2; i++) {
      int id = tid + i * NTHR, r = id >> 2, c = id & 3;
      cpasync16(dst + sw_off(r, c), g + (size_t)(c0 + r) * ldb + kt + c * 8);
    }
  };
  auto load_stage = [&](int s, int kt) {
    unsigned b = sbase + s * STG;
    load_A(b, A, kt);
    if constexpr (SPLIT) load_A(b + ATB, A2, kt);
    load_B(b + (SPLIT ? 2 : 1) * ATB, B, kt);
    cp_commit();
  };

  float acc[4][4][4];
#pragma unroll
  for (int i = 0; i < 4; i++)
#pragma unroll
    for (int j = 0; j < 4; j++)
#pragma unroll
      for (int r = 0; r < 4; r++) acc[i][j][r] = 0.f;

#pragma unroll
  for (int s = 0; s < NST - 1; s++) load_stage(s, s * BK);

  const int q = lane >> 2, t2 = lane & 3;
  const int sw = lane >> 3;  // == (r>>1)&3 for all rows this thread touches
  const unsigned fb = (unsigned)(t2 * 4);

  for (int k = 0; k < nk; k++) {
    cp_wait<NST - 2>();
    __syncthreads();
    if (k + NST - 1 < nk) load_stage((k + NST - 1) % NST, (k + NST - 1) * BK);
    else cp_commit();  // keep group count consistent

    const unsigned sb = sbase + (unsigned)((k % NST) * STG);
    const unsigned sA = sb, sA2 = sb + ATB;
    const unsigned sB = sb + (SPLIT ? 2 : 1) * ATB;

#pragma unroll
    for (int ks = 0; ks < 2; ks++) {
      const int kc0 = ks * 2;
      const unsigned ch0 = (unsigned)((kc0 ^ sw) << 4);
      const unsigned ch1 = (unsigned)(((kc0 + 1) ^ sw) << 4);

      uint32_t ah[4][4], bh[4][2];
#pragma unroll
      for (int ma = 0; ma < 4; ma++) {
        unsigned rb0 = sA + (unsigned)((wm + ma * 16 + q) * 64) + fb;
        unsigned rb1 = rb0 + 8 * 64;
        ah[ma][0] = lds32(rb0 + ch0);
        ah[ma][1] = lds32(rb1 + ch0);
        ah[ma][2] = lds32(rb0 + ch1);
        ah[ma][3] = lds32(rb1 + ch1);
      }
#pragma unroll
      for (int na = 0; na < 4; na++) {
        unsigned nb = sB + (unsigned)((wn + na * 8 + q) * 64) + fb;
        bh[na][0] = lds32(nb + ch0);
        bh[na][1] = lds32(nb + ch1);
      }
#pragma unroll
      for (int ma = 0; ma < 4; ma++)
#pragma unroll
        for (int na = 0; na < 4; na++) mma16(acc[ma][na], ah[ma], bh[na]);

      if constexpr (SPLIT) {
        uint32_t al[4][4];
#pragma unroll
        for (int ma = 0; ma < 4; ma++) {
          unsigned rb0 = sA2 + (unsigned)((wm + ma * 16 + q) * 64) + fb;
          unsigned rb1 = rb0 + 8 * 64;
          al[ma][0] = lds32(rb0 + ch0);
          al[ma][1] = lds32(rb1 + ch0);
          al[ma][2] = lds32(rb0 + ch1);
          al[ma][3] = lds32(rb1 + ch1);
        }
#pragma unroll
        for (int ma = 0; ma < 4; ma++)
#pragma unroll
          for (int na = 0; na < 4; na++) mma16(acc[ma][na], al[ma], bh[na]);
      }
    }
  }

  // ---- epilogue ----
#pragma unroll
  for (int ma = 0; ma < 4; ma++) {
#pragma unroll
    for (int na = 0; na < 4; na++) {
      const int row = r0 + wm + ma * 16 + q;
      const int col = c0 + wn + na * 8 + t2 * 2;
      float v0 = acc[ma][na][0], v1 = acc[ma][na][1];
      float v2 = acc[ma][na][2], v3 = acc[ma][na][3];
      if constexpr (EPI == 1) {
        __half* D = (__half*)Dv;
        float b0 = bias[col], b1 = bias[col + 1];
        *(__half2*)(D + (size_t)row * ldd + col) = __floats2half2_rn(v0 + b0, v1 + b1);
        *(__half2*)(D + (size_t)(row + 8) * ldd + col) = __floats2half2_rn(v2 + b0, v3 + b1);
      } else {
        float* D = (float*)Dv;
        *(float2*)(D + (size_t)row * ldd + col) = make_float2(v0 * scale, v1 * scale);
        *(float2*)(D + (size_t)(row + 8) * ldd + col) = make_float2(v2 * scale, v3 * scale);
      }
    }
  }
}

// ---------------------------------------------------------------------------
// Prep kernels
// ---------------------------------------------------------------------------
__global__ __launch_bounds__(256) void split_x(const float* __restrict__ in,
                                               __half* __restrict__ hi,
                                               __half* __restrict__ lo, int n4) {
  int i = blockIdx.x * 256 + threadIdx.x;
  if (i >= n4) return;
  float4 v = ((const float4*)in)[i];
  __half h0 = __float2half_rn(v.x), h1 = __float2half_rn(v.y);
  __half h2 = __float2half_rn(v.z), h3 = __float2half_rn(v.w);
  __half2* hp = (__half2*)(hi + (size_t)i * 4);
  hp[0] = __halves2half2(h0, h1);
  hp[1] = __halves2half2(h2, h3);
  __half2* lp = (__half2*)(lo + (size_t)i * 4);
  lp[0] = __halves2half2(__float2half_rn(v.x - __half2float(h0)),
                         __float2half_rn(v.y - __half2float(h1)));
  lp[1] = __halves2half2(__float2half_rn(v.z - __half2float(h2)),
                         __float2half_rn(v.w - __half2float(h3)));
}

// W [C, N3] float -> W^T [N3, C] fp16 hi (lo not needed: dropped term)
__global__ __launch_bounds__(256) void transpose_w(const float* __restrict__ W,
                                                   __half* __restrict__ oh) {
  __shared__ float t[32][33];
  const int bx = blockIdx.x * 32, by = blockIdx.y * 32;
  const int tx = threadIdx.x & 31, ty = threadIdx.x >> 5;
#pragma unroll
  for (int i = 0; i < 4; i++)
    t[ty + i * 8][tx] = W[(size_t)(by + ty + i * 8) * N3_DIM + bx + tx];
  __syncthreads();
#pragma unroll
  for (int i = 0; i < 4; i++) {
    float v = t[tx][ty + i * 8];
    oh[(size_t)(bx + ty + i * 8) * C_DIM + by + tx] = __float2half_rn(v);
  }
}

// v (qkv cols [4096,6144)) half -> v^T [NF, T] half
__global__ __launch_bounds__(256) void transpose_v(const __half* __restrict__ qkv,
                                                   __half* __restrict__ vt) {
  __shared__ __half t[32][34];
  const int bx = blockIdx.x * 32, by = blockIdx.y * 32;
  const int tx = threadIdx.x & 31, ty = threadIdx.x >> 5;
#pragma unroll
  for (int i = 0; i < 4; i++)
    t[ty + i * 8][tx] = qkv[(size_t)(by + ty + i * 8) * N3_DIM + 2 * NF_DIM + bx + tx];
  __syncthreads();
#pragma unroll
  for (int i = 0; i < 4; i++)
    vt[(size_t)(bx + ty + i * 8) * T_DIM + by + tx] = t[tx][ty + i * 8];
}

// ---------------------------------------------------------------------------
// Row softmax over [n_padd, row]; writes P*2^14 fp16; zeros elsewhere.
// Single exp evaluation: pass2 stores unnormalized exp, pass3 rescales.
// ---------------------------------------------------------------------------
__global__ void softmax_rows(const float* __restrict__ S, __half* __restrict__ P,
                             const int* __restrict__ npad_p) {
  const int row = blockIdx.x;
  const int tid = threadIdx.x;
  const int npad = *npad_p;
  const float* rp = S + (size_t)row * T_DIM;
  __half* pp = P + (size_t)row * T_DIM;
  __shared__ float red[8];
  if (row < npad) {
    for (int c = tid; c < T_DIM; c += 256) pp[c] = __float2half(0.f);
    return;
  }
  const int lo = npad, hi = row;
  float m = -3.0e38f;
  for (int c = lo + tid; c <= hi; c += 256) m = fmaxf(m, rp[c]);
#pragma unroll
  for (int o = 16; o > 0; o >>= 1) m = fmaxf(m, __shfl_xor_sync(0xffffffffu, m, o));
  if ((tid & 31) == 0) red[tid >> 5] = m;
  __syncthreads();
  float bmax = red[0];
#pragma unroll
  for (int i = 1; i < 8; i++) bmax = fmaxf(bmax, red[i]);
  __syncthreads();
  float s = 0.f;
  for (int c = lo + tid; c <= hi; c += 256) {
    float e = __expf(rp[c] - bmax) * 16384.0f;  // pre-scale by 2^14 (exact)
    pp[c] = __float2half_rn(e);
    s += e;
  }
#pragma unroll
  for (int o = 16; o > 0; o >>= 1) s += __shfl_xor_sync(0xffffffffu, s, o);
  if ((tid & 31) == 0) red[tid >> 5] = s;
  __syncthreads();
  float bsum = 0.f;
#pragma unroll
  for (int i = 0; i < 8; i++) bsum += red[i];
  const float inv = 16384.0f / bsum;  // final P = e/bsum * 2^14
  for (int c = tid; c < T_DIM; c += 256) {
    float v = (c >= lo && c <= hi) ? __half2float(pp[c]) * inv : 0.f;
    pp[c] = __float2half_rn(v);
  }
}

extern "C" void kernel_launch(void* const* d_in, const int* in_sizes, int n_in,
                              void* d_out, int out_size) {
  const float* x = (const float*)d_in[0];
  const float* W = (const float*)d_in[1];
  const float* bias = (const float*)d_in[2];
  const int* n_padd = (const int*)d_in[3];
  float* y = (float*)d_out;

  __half *qkv, *P, *vt, *xh, *xl, *wth;
  float* S;
  cudaGetSymbolAddress((void**)&qkv, g_qkv);
  cudaGetSymbolAddress((void**)&S, g_S);
  cudaGetSymbolAddress((void**)&P, g_P);
  cudaGetSymbolAddress((void**)&xh, g_xh);
  cudaGetSymbolAddress((void**)&xl, g_xl);
  cudaGetSymbolAddress((void**)&wth, g_wth);
  cudaGetSymbolAddress((void**)&vt, g_vt);

  const float scale = 1.0f / sqrtf((float)NF_DIM);

  constexpr int SM_SINGLE = NST * (BM * 64 + BN * 64);            // 73728
  constexpr int SM_SPLIT = NST * (2 * BM * 64 + BN * 64);         // 98304

  cudaFuncSetAttribute((const void*)gemm_h<1, false, false, true>,
                       cudaFuncAttributeMaxDynamicSharedMemorySize, SM_SPLIT);
  cudaFuncSetAttribute((const void*)gemm_h<0, true, false, false>,
                       cudaFuncAttributeMaxDynamicSharedMemorySize, SM_SINGLE);
  cudaFuncSetAttribute((const void*)gemm_h<0, false, true, false>,
                       cudaFuncAttributeMaxDynamicSharedMemorySize, SM_SINGLE);

  // Prep: x -> fp16 hi/lo ; W -> W^T fp16 hi
  split_x<<<(T_DIM * C_DIM / 4 + 255) / 256, 256>>>(x, xh, xl, T_DIM * C_DIM / 4);
  transpose_w<<<dim3(N3_DIM / 32, C_DIM / 32), 256>>>(W, wth);

  // GEMM1: qkv = x @ W + b   (fp16x2: (x_hi + x_lo) @ W_hi; writes fp16)
  gemm_h<1, false, false, true>
      <<<dim3(N3_DIM / BN, T_DIM / BM), NTHR, SM_SPLIT>>>(
          (const uint16_t*)xh, (const uint16_t*)wth, (const uint16_t*)xl,
          qkv, bias, 0.f, C_DIM, C_DIM, C_DIM, N3_DIM);

  // v^T
  transpose_v<<<dim3(NF_DIM / 32, T_DIM / 32), 256>>>(qkv, vt);

  // GEMM2: S = (q @ k^T) * scale   (causal block skip)
  gemm_h<0, true, false, false>
      <<<dim3(T_DIM / BN, T_DIM / BM), NTHR, SM_SINGLE>>>(
          (const uint16_t*)qkv, (const uint16_t*)(qkv + NF_DIM), nullptr,
          S, nullptr, scale, NF_DIM, N3_DIM, N3_DIM, T_DIM);

  // Softmax -> P (fp16, *2^14, single exp)
  softmax_rows<<<T_DIM, 256>>>(S, P, n_padd);

  // GEMM3: y = P @ v * 2^-14   (causal K bound)
  gemm_h<0, false, true, false>
      <<<dim3(NF_DIM / BN, T_DIM / BM), NTHR, SM_SINGLE>>>(
          (const uint16_t*)P, (const uint16_t*)vt, nullptr,
          y, nullptr, 6.103515625e-05f, T_DIM, T_DIM, T_DIM, NF_DIM);
}

// round 9
// speedup vs baseline: 3.0870x; 1.2299x over previous
#include <cuda_runtime.h>
#include <cuda_fp16.h>
#include <math.h>
#include <cstdint>

#define T_DIM 4096
#define C_DIM 2048
#define NF_DIM 2048
#define N3_DIM 6144

constexpr int BM = 128, BN = 256, BK = 32;  // BK in half-elements (64B rows)
constexpr int NST = 4;                       // pipeline stages
constexpr int NTHR = 512;                    // 16 warps: 2(M) x 8(N) of 64x32

// Scratch (allocation-free rule: __device__ globals)
__device__ __half g_qkv[(size_t)T_DIM * N3_DIM];   // fp16 qkv (48 MB)
__device__ float g_S[(size_t)T_DIM * T_DIM];       // att logits (64 MB)
__device__ __half g_P[(size_t)T_DIM * T_DIM];      // P (fp16, *2^14)
__device__ __half g_xh[(size_t)T_DIM * C_DIM];     // x fp16
__device__ __half g_wth[(size_t)N3_DIM * C_DIM];   // W^T fp16
__device__ __half g_vt[(size_t)NF_DIM * T_DIM];    // v^T fp16

__device__ __forceinline__ void cpasync16(unsigned s, const void* g) {
  asm volatile("cp.async.cg.shared.global [%0], [%1], 16;\n" ::"r"(s), "l"(g));
}
__device__ __forceinline__ void cp_commit() { asm volatile("cp.async.commit_group;\n" ::); }
template <int N>
__device__ __forceinline__ void cp_wait() {
  asm volatile("cp.async.wait_group %0;\n" ::"n"(N));
}
__device__ __forceinline__ uint32_t lds32(unsigned a) {
  uint32_t v;
  asm volatile("ld.shared.b32 %0, [%1];" : "=r"(v) : "r"(a));
  return v;
}
__device__ __forceinline__ void mma16(float (&c)[4], const uint32_t (&a)[4],
                                      const uint32_t (&b)[2]) {
  asm volatile(
      "mma.sync.aligned.m16n8k16.row.col.f32.f16.f16.f32 "
      "{%0,%1,%2,%3}, {%4,%5,%6,%7}, {%8,%9}, {%0,%1,%2,%3};\n"
      : "+f"(c[0]), "+f"(c[1]), "+f"(c[2]), "+f"(c[3])
      : "r"(a[0]), "r"(a[1]), "r"(a[2]), "r"(a[3]), "r"(b[0]), "r"(b[1]));
}

// ---------------------------------------------------------------------------
// fp16 NT GEMM: D[M,N] = A[M,K] @ B[N,K]^T   (fp32 accum)
// CTA 128x256, 16 warps of 64x32, BK=32 halves, XOR-swizzled 64B smem rows.
// EPI: 0 -> float out * scale ; 1 -> half out + bias
// CSKIP: causal block skip (GEMM2)   CK: causal K bound (GEMM3)
// ---------------------------------------------------------------------------
template <int EPI, bool CSKIP, bool CK>
__global__ __launch_bounds__(NTHR, 1) void gemm_h(
    const uint16_t* __restrict__ A, const uint16_t* __restrict__ B,
    void* __restrict__ Dv, const float* __restrict__ bias, float scale,
    int K, int lda, int ldb, int ldd) {
  constexpr int ATB = BM * 64;   // 8 KB A tile
  constexpr int BTB = BN * 64;   // 16 KB B tile
  constexpr int STG = ATB + BTB;
  extern __shared__ __align__(16) char smem[];

  const int r0 = blockIdx.y * BM, c0 = blockIdx.x * BN;
  if (CSKIP && c0 > r0 + BM - 1) return;
  const int kend = CK ? min(K, r0 + BM) : K;
  const int nk = kend / BK;

  const int tid = threadIdx.x, lane = tid & 31, warp = tid >> 5;
  const int wm = (warp >> 3) * 64, wn = (warp & 7) * 32;
  const unsigned sbase = (unsigned)__cvta_generic_to_shared(smem);

  auto sw_off = [](int r, int c) {
    return (unsigned)(r * 64 + ((c ^ ((r >> 1) & 3)) << 4));
  };
  auto load_stage = [&](int s, int kt) {
    unsigned b = sbase + s * STG;
    {
      int r = tid >> 2, c = tid & 3;  // A: 128 rows x 4 chunks = 512
      cpasync16(b + sw_off(r, c), A + (size_t)(r0 + r) * lda + kt + c * 8);
    }
#pragma unroll
    for (int i = 0; i < 2; i++) {     // B: 256 rows x 4 chunks = 1024
      int id = tid + i * NTHR, r = id >> 2, c = id & 3;
      cpasync16(b + ATB + sw_off(r, c), B + (size_t)(c0 + r) * ldb + kt + c * 8);
    }
    cp_commit();
  };

  float acc[4][4][4];
#pragma unroll
  for (int i = 0; i < 4; i++)
#pragma unroll
    for (int j = 0; j < 4; j++)
#pragma unroll
      for (int r = 0; r < 4; r++) acc[i][j][r] = 0.f;

#pragma unroll
  for (int s = 0; s < NST - 1; s++) load_stage(s, s * BK);

  const int q = lane >> 2, t2 = lane & 3;
  const int sw = lane >> 3;  // == (r>>1)&3 for all rows this thread touches
  const unsigned fb = (unsigned)(t2 * 4);

  for (int k = 0; k < nk; k++) {
    cp_wait<NST - 2>();
    __syncthreads();
    if (k + NST - 1 < nk) load_stage((k + NST - 1) % NST, (k + NST - 1) * BK);
    else cp_commit();  // keep group count consistent

    const unsigned sb = sbase + (unsigned)((k % NST) * STG);
    const unsigned sA = sb, sB = sb + ATB;

#pragma unroll
    for (int ks = 0; ks < 2; ks++) {
      const int kc0 = ks * 2;
      const unsigned ch0 = (unsigned)((kc0 ^ sw) << 4);
      const unsigned ch1 = (unsigned)(((kc0 + 1) ^ sw) << 4);

      uint32_t ah[4][4], bh[4][2];
#pragma unroll
      for (int ma = 0; ma < 4; ma++) {
        unsigned rb0 = sA + (unsigned)((wm + ma * 16 + q) * 64) + fb;
        unsigned rb1 = rb0 + 8 * 64;
        ah[ma][0] = lds32(rb0 + ch0);
        ah[ma][1] = lds32(rb1 + ch0);
        ah[ma][2] = lds32(rb0 + ch1);
        ah[ma][3] = lds32(rb1 + ch1);
      }
#pragma unroll
      for (int na = 0; na < 4; na++) {
        unsigned nb = sB + (unsigned)((wn + na * 8 + q) * 64) + fb;
        bh[na][0] = lds32(nb + ch0);
        bh[na][1] = lds32(nb + ch1);
      }
#pragma unroll
      for (int ma = 0; ma < 4; ma++)
#pragma unroll
        for (int na = 0; na < 4; na++) mma16(acc[ma][na], ah[ma], bh[na]);
    }
  }

  // ---- epilogue ----
#pragma unroll
  for (int ma = 0; ma < 4; ma++) {
#pragma unroll
    for (int na = 0; na < 4; na++) {
      const int row = r0 + wm + ma * 16 + q;
      const int col = c0 + wn + na * 8 + t2 * 2;
      float v0 = acc[ma][na][0], v1 = acc[ma][na][1];
      float v2 = acc[ma][na][2], v3 = acc[ma][na][3];
      if constexpr (EPI == 1) {
        __half* D = (__half*)Dv;
        float b0 = bias[col], b1 = bias[col + 1];
        *(__half2*)(D + (size_t)row * ldd + col) = __floats2half2_rn(v0 + b0, v1 + b1);
        *(__half2*)(D + (size_t)(row + 8) * ldd + col) = __floats2half2_rn(v2 + b0, v3 + b1);
      } else {
        float* D = (float*)Dv;
        *(float2*)(D + (size_t)row * ldd + col) = make_float2(v0 * scale, v1 * scale);
        *(float2*)(D + (size_t)(row + 8) * ldd + col) = make_float2(v2 * scale, v3 * scale);
      }
    }
  }
}

// ---------------------------------------------------------------------------
// Prep kernels
// ---------------------------------------------------------------------------
__global__ __launch_bounds__(256) void conv_x(const float* __restrict__ in,
                                              __half* __restrict__ out, int n4) {
  int i = blockIdx.x * 256 + threadIdx.x;
  if (i >= n4) return;
  float4 v = ((const float4*)in)[i];
  __half2* op = (__half2*)(out + (size_t)i * 4);
  op[0] = __floats2half2_rn(v.x, v.y);
  op[1] = __floats2half2_rn(v.z, v.w);
}

// W [C, N3] float -> W^T [N3, C] fp16
__global__ __launch_bounds__(256) void transpose_w(const float* __restrict__ W,
                                                   __half* __restrict__ oh) {
  __shared__ float t[32][33];
  const int bx = blockIdx.x * 32, by = blockIdx.y * 32;
  const int tx = threadIdx.x & 31, ty = threadIdx.x >> 5;
#pragma unroll
  for (int i = 0; i < 4; i++)
    t[ty + i * 8][tx] = W[(size_t)(by + ty + i * 8) * N3_DIM + bx + tx];
  __syncthreads();
#pragma unroll
  for (int i = 0; i < 4; i++) {
    float v = t[tx][ty + i * 8];
    oh[(size_t)(bx + ty + i * 8) * C_DIM + by + tx] = __float2half_rn(v);
  }
}

// v (qkv cols [4096,6144)) half -> v^T [NF, T] half
__global__ __launch_bounds__(256) void transpose_v(const __half* __restrict__ qkv,
                                                   __half* __restrict__ vt) {
  __shared__ __half t[32][34];
  const int bx = blockIdx.x * 32, by = blockIdx.y * 32;
  const int tx = threadIdx.x & 31, ty = threadIdx.x >> 5;
#pragma unroll
  for (int i = 0; i < 4; i++)
    t[ty + i * 8][tx] = qkv[(size_t)(by + ty + i * 8) * N3_DIM + 2 * NF_DIM + bx + tx];
  __syncthreads();
#pragma unroll
  for (int i = 0; i < 4; i++)
    vt[(size_t)(bx + ty + i * 8) * T_DIM + by + tx] = t[tx][ty + i * 8];
}

// ---------------------------------------------------------------------------
// Row softmax over [n_padd, row]; writes P*2^14 fp16 up to the 128-aligned
// row-tile bound (GEMM3 never reads beyond min(K, r0+128)); single exp pass.
// ---------------------------------------------------------------------------
__global__ void softmax_rows(const float* __restrict__ S, __half* __restrict__ P,
                             const int* __restrict__ npad_p) {
  const int row = blockIdx.x;
  const int tid = threadIdx.x;
  const int npad = *npad_p;
  const float* rp = S + (size_t)row * T_DIM;
  __half* pp = P + (size_t)row * T_DIM;
  const int wend = ((row >> 7) + 1) << 7;  // GEMM3 read bound for this row
  __shared__ float red[8];
  if (row < npad) {
    for (int c = tid; c < wend; c += 256) pp[c] = __float2half(0.f);
    return;
  }
  const int lo = npad, hi = row;
  float m = -3.0e38f;
  for (int c = lo + tid; c <= hi; c += 256) m = fmaxf(m, rp[c]);
#pragma unroll
  for (int o = 16; o > 0; o >>= 1) m = fmaxf(m, __shfl_xor_sync(0xffffffffu, m, o));
  if ((tid & 31) == 0) red[tid >> 5] = m;
  __syncthreads();
  float bmax = red[0];
#pragma unroll
  for (int i = 1; i < 8; i++) bmax = fmaxf(bmax, red[i]);
  __syncthreads();
  float s = 0.f;
  for (int c = lo + tid; c <= hi; c += 256) {
    float e = __expf(rp[c] - bmax) * 16384.0f;  // pre-scale by 2^14 (exact)
    pp[c] = __float2half_rn(e);
    s += e;
  }
#pragma unroll
  for (int o = 16; o > 0; o >>= 1) s += __shfl_xor_sync(0xffffffffu, s, o);
  if ((tid & 31) == 0) red[tid >> 5] = s;
  __syncthreads();
  float bsum = 0.f;
#pragma unroll
  for (int i = 0; i < 8; i++) bsum += red[i];
  const float inv = 16384.0f / bsum;  // final P = e/bsum * 2^14
  for (int c = tid; c < wend; c += 256) {
    float v = (c >= lo && c <= hi) ? __half2float(pp[c]) * inv : 0.f;
    pp[c] = __float2half_rn(v);
  }
}

extern "C" void kernel_launch(void* const* d_in, const int* in_sizes, int n_in,
                              void* d_out, int out_size) {
  const float* x = (const float*)d_in[0];
  const float* W = (const float*)d_in[1];
  const float* bias = (const float*)d_in[2];
  const int* n_padd = (const int*)d_in[3];
  float* y = (float*)d_out;

  __half *qkv, *P, *vt, *xh, *wth;
  float* S;
  cudaGetSymbolAddress((void**)&qkv, g_qkv);
  cudaGetSymbolAddress((void**)&S, g_S);
  cudaGetSymbolAddress((void**)&P, g_P);
  cudaGetSymbolAddress((void**)&xh, g_xh);
  cudaGetSymbolAddress((void**)&wth, g_wth);
  cudaGetSymbolAddress((void**)&vt, g_vt);

  const float scale = 1.0f / sqrtf((float)NF_DIM);

  constexpr int SM_BYTES = NST * (BM * 64 + BN * 64);  // 98304

  cudaFuncSetAttribute((const void*)gemm_h<1, false, false>,
                       cudaFuncAttributeMaxDynamicSharedMemorySize, SM_BYTES);
  cudaFuncSetAttribute((const void*)gemm_h<0, true, false>,
                       cudaFuncAttributeMaxDynamicSharedMemorySize, SM_BYTES);
  cudaFuncSetAttribute((const void*)gemm_h<0, false, true>,
                       cudaFuncAttributeMaxDynamicSharedMemorySize, SM_BYTES);

  // Prep: x -> fp16 ; W -> W^T fp16
  conv_x<<<(T_DIM * C_DIM / 4 + 255) / 256, 256>>>(x, xh, T_DIM * C_DIM / 4);
  transpose_w<<<dim3(N3_DIM / 32, C_DIM / 32), 256>>>(W, wth);

  // GEMM1: qkv = x @ W + b   (single fp16 pass; writes fp16)
  gemm_h<1, false, false><<<dim3(N3_DIM / BN, T_DIM / BM), NTHR, SM_BYTES>>>(
      (const uint16_t*)xh, (const uint16_t*)wth, qkv, bias, 0.f,
      C_DIM, C_DIM, C_DIM, N3_DIM);

  // v^T
  transpose_v<<<dim3(NF_DIM / 32, T_DIM / 32), 256>>>(qkv, vt);

  // GEMM2: S = (q @ k^T) * scale   (causal block skip)
  gemm_h<0, true, false><<<dim3(T_DIM / BN, T_DIM / BM), NTHR, SM_BYTES>>>(
      (const uint16_t*)qkv, (const uint16_t*)(qkv + NF_DIM),
      S, nullptr, scale, NF_DIM, N3_DIM, N3_DIM, T_DIM);

  // Softmax -> P (fp16, *2^14, single exp, tile-bounded writes)
  softmax_rows<<<T_DIM, 256>>>(S, P, n_padd);

  // GEMM3: y = P @ v * 2^-14   (causal K bound)
  gemm_h<0, false, true><<<dim3(NF_DIM / BN, T_DIM / BM), NTHR, SM_BYTES>>>(
      (const uint16_t*)P, (const uint16_t*)vt,
      y, nullptr, 6.103515625e-05f, T_DIM, T_DIM, T_DIM, NF_DIM);
}

// round 10
// speedup vs baseline: 3.6345x; 1.1773x over previous
#include <cuda_runtime.h>
#include <cuda_fp16.h>
#include <math.h>
#include <cstdint>

#define T_DIM 4096
#define C_DIM 2048
#define NF_DIM 2048
#define N3_DIM 6144

constexpr int BM = 128, BN = 256, BK = 32;  // BK in half-elements (64B rows)
constexpr int NST = 4;                       // pipeline stages
constexpr int NTHR = 512;                    // 16 warps: 2(M) x 8(N) of 64x32

// Scratch (allocation-free rule: __device__ globals)
__device__ __half g_qkv[(size_t)T_DIM * N3_DIM];   // fp16 qkv (48 MB)
__device__ float g_S[(size_t)T_DIM * T_DIM];       // att logits (64 MB)
__device__ __half g_P[(size_t)T_DIM * T_DIM];      // P (fp16, *2^14)
__device__ __half g_xh[(size_t)T_DIM * C_DIM];     // x fp16
__device__ __half g_wth[(size_t)N3_DIM * C_DIM];   // W^T fp16
__device__ __half g_vt[(size_t)NF_DIM * T_DIM];    // v^T fp16

__device__ __forceinline__ void cpasync16(unsigned s, const void* g) {
  asm volatile("cp.async.cg.shared.global [%0], [%1], 16;\n" ::"r"(s), "l"(g));
}
__device__ __forceinline__ void cp_commit() { asm volatile("cp.async.commit_group;\n" ::); }
template <int N>
__device__ __forceinline__ void cp_wait() {
  asm volatile("cp.async.wait_group %0;\n" ::"n"(N));
}
__device__ __forceinline__ void ldsm4(uint32_t& r0, uint32_t& r1, uint32_t& r2,
                                      uint32_t& r3, unsigned addr) {
  asm volatile("ldmatrix.sync.aligned.m8n8.x4.shared.b16 {%0,%1,%2,%3}, [%4];"
               : "=r"(r0), "=r"(r1), "=r"(r2), "=r"(r3)
               : "r"(addr));
}
__device__ __forceinline__ void mma16(float (&c)[4], const uint32_t (&a)[4],
                                      const uint32_t (&b)[2]) {
  asm volatile(
      "mma.sync.aligned.m16n8k16.row.col.f32.f16.f16.f32 "
      "{%0,%1,%2,%3}, {%4,%5,%6,%7}, {%8,%9}, {%0,%1,%2,%3};\n"
      : "+f"(c[0]), "+f"(c[1]), "+f"(c[2]), "+f"(c[3])
      : "r"(a[0]), "r"(a[1]), "r"(a[2]), "r"(a[3]), "r"(b[0]), "r"(b[1]));
}

// ---------------------------------------------------------------------------
// fp16 NT GEMM: D[M,N] = A[M,K] @ B[N,K]^T   (fp32 accum)
// CTA 128x256, 16 warps of 64x32, BK=32 halves, XOR-swizzled 64B smem rows.
// Fragments loaded via ldmatrix.x4.
// EPI: 0 -> float out * scale ; 1 -> half out + bias
// CSKIP: causal block skip (GEMM2)   CK: causal K bound (GEMM3)
// ---------------------------------------------------------------------------
template <int EPI, bool CSKIP, bool CK>
__global__ __launch_bounds__(NTHR, 1) void gemm_h(
    const uint16_t* __restrict__ A, const uint16_t* __restrict__ B,
    void* __restrict__ Dv, const float* __restrict__ bias, float scale,
    int K, int lda, int ldb, int ldd) {
  constexpr int ATB = BM * 64;   // 8 KB A tile
  constexpr int BTB = BN * 64;   // 16 KB B tile
  constexpr int STG = ATB + BTB;
  extern __shared__ __align__(16) char smem[];

  const int r0 = blockIdx.y * BM, c0 = blockIdx.x * BN;
  if (CSKIP && c0 > r0 + BM - 1) return;
  const int kend = CK ? min(K, r0 + BM) : K;
  const int nk = kend / BK;

  const int tid = threadIdx.x, lane = tid & 31, warp = tid >> 5;
  const int wm = (warp >> 3) * 64, wn = (warp & 7) * 32;
  const unsigned sbase = (unsigned)__cvta_generic_to_shared(smem);

  auto sw_off = [](int r, int c) {
    return (unsigned)(r * 64 + ((c ^ ((r >> 1) & 3)) << 4));
  };
  auto load_stage = [&](int s, int kt) {
    unsigned b = sbase + s * STG;
    {
      int r = tid >> 2, c = tid & 3;  // A: 128 rows x 4 chunks = 512
      cpasync16(b + sw_off(r, c), A + (size_t)(r0 + r) * lda + kt + c * 8);
    }
#pragma unroll
    for (int i = 0; i < 2; i++) {     // B: 256 rows x 4 chunks = 1024
      int id = tid + i * NTHR, r = id >> 2, c = id & 3;
      cpasync16(b + ATB + sw_off(r, c), B + (size_t)(c0 + r) * ldb + kt + c * 8);
    }
    cp_commit();
  };

  float acc[4][4][4];
#pragma unroll
  for (int i = 0; i < 4; i++)
#pragma unroll
    for (int j = 0; j < 4; j++)
#pragma unroll
      for (int r = 0; r < 4; r++) acc[i][j][r] = 0.f;

#pragma unroll
  for (int s = 0; s < NST - 1; s++) load_stage(s, s * BK);

  // --- per-thread ldmatrix address components ---
  // A x4: lanes 0-15 -> rows (lane&15), chunk kc0; lanes 16-31 -> same rows, kc0+1
  const int cA = lane >> 4;
  unsigned aoff[4];
  int ax[4];
#pragma unroll
  for (int ma = 0; ma < 4; ma++) {
    int rowA = wm + ma * 16 + (lane & 15);
    aoff[ma] = (unsigned)(rowA * 64);
    ax[ma] = (rowA >> 1) & 3;
  }
  // B x4 (two n8 tiles per instr): lanes 0-7 n0 rows kc0; 8-15 n0 rows kc0+1;
  //                                16-23 n1 rows kc0; 24-31 n1 rows kc0+1
  const int cB = (lane >> 3) & 1;
  unsigned boff[2];
  int bx[2];
#pragma unroll
  for (int np = 0; np < 2; np++) {
    int rowB = wn + np * 16 + ((lane >> 4) * 8) + (lane & 7);
    boff[np] = (unsigned)(rowB * 64);
    bx[np] = (rowB >> 1) & 3;
  }

  for (int k = 0; k < nk; k++) {
    cp_wait<NST - 2>();
    __syncthreads();
    if (k + NST - 1 < nk) load_stage((k + NST - 1) % NST, (k + NST - 1) * BK);
    else cp_commit();  // keep group count consistent

    const unsigned sb = sbase + (unsigned)((k % NST) * STG);
    const unsigned sA = sb, sB = sb + ATB;

#pragma unroll
    for (int ks = 0; ks < 2; ks++) {
      const int kc0 = ks * 2;
      uint32_t ah[4][4], bh[4][2];
#pragma unroll
      for (int ma = 0; ma < 4; ma++)
        ldsm4(ah[ma][0], ah[ma][1], ah[ma][2], ah[ma][3],
              sA + aoff[ma] + (unsigned)(((kc0 + cA) ^ ax[ma]) << 4));
#pragma unroll
      for (int np = 0; np < 2; np++)
        ldsm4(bh[2 * np][0], bh[2 * np][1], bh[2 * np + 1][0], bh[2 * np + 1][1],
              sB + boff[np] + (unsigned)(((kc0 + cB) ^ bx[np]) << 4));
#pragma unroll
      for (int ma = 0; ma < 4; ma++)
#pragma unroll
        for (int na = 0; na < 4; na++) mma16(acc[ma][na], ah[ma], bh[na]);
    }
  }

  // ---- epilogue ----
  const int q = lane >> 2, t2 = lane & 3;
#pragma unroll
  for (int ma = 0; ma < 4; ma++) {
#pragma unroll
    for (int na = 0; na < 4; na++) {
      const int row = r0 + wm + ma * 16 + q;
      const int col = c0 + wn + na * 8 + t2 * 2;
      float v0 = acc[ma][na][0], v1 = acc[ma][na][1];
      float v2 = acc[ma][na][2], v3 = acc[ma][na][3];
      if constexpr (EPI == 1) {
        __half* D = (__half*)Dv;
        float b0 = bias[col], b1 = bias[col + 1];
        *(__half2*)(D + (size_t)row * ldd + col) = __floats2half2_rn(v0 + b0, v1 + b1);
        *(__half2*)(D + (size_t)(row + 8) * ldd + col) = __floats2half2_rn(v2 + b0, v3 + b1);
      } else {
        float* D = (float*)Dv;
        *(float2*)(D + (size_t)row * ldd + col) = make_float2(v0 * scale, v1 * scale);
        *(float2*)(D + (size_t)(row + 8) * ldd + col) = make_float2(v2 * scale, v3 * scale);
      }
    }
  }
}

// ---------------------------------------------------------------------------
// Prep kernels
// ---------------------------------------------------------------------------
__global__ __launch_bounds__(256) void conv_x(const float* __restrict__ in,
                                              __half* __restrict__ out, int n4) {
  int i = blockIdx.x * 256 + threadIdx.x;
  if (i >= n4) return;
  float4 v = ((const float4*)in)[i];
  __half2* op = (__half2*)(out + (size_t)i * 4);
  op[0] = __floats2half2_rn(v.x, v.y);
  op[1] = __floats2half2_rn(v.z, v.w);
}

// W [C, N3] float -> W^T [N3, C] fp16
__global__ __launch_bounds__(256) void transpose_w(const float* __restrict__ W,
                                                   __half* __restrict__ oh) {
  __shared__ float t[32][33];
  const int bx = blockIdx.x * 32, by = blockIdx.y * 32;
  const int tx = threadIdx.x & 31, ty = threadIdx.x >> 5;
#pragma unroll
  for (int i = 0; i < 4; i++)
    t[ty + i * 8][tx] = W[(size_t)(by + ty + i * 8) * N3_DIM + bx + tx];
  __syncthreads();
#pragma unroll
  for (int i = 0; i < 4; i++) {
    float v = t[tx][ty + i * 8];
    oh[(size_t)(bx + ty + i * 8) * C_DIM + by + tx] = __float2half_rn(v);
  }
}

// v (qkv cols [4096,6144)) half -> v^T [NF, T] half
__global__ __launch_bounds__(256) void transpose_v(const __half* __restrict__ qkv,
                                                   __half* __restrict__ vt) {
  __shared__ __half t[32][34];
  const int bx = blockIdx.x * 32, by = blockIdx.y * 32;
  const int tx = threadIdx.x & 31, ty = threadIdx.x >> 5;
#pragma unroll
  for (int i = 0; i < 4; i++)
    t[ty + i * 8][tx] = qkv[(size_t)(by + ty + i * 8) * N3_DIM + 2 * NF_DIM + bx + tx];
  __syncthreads();
#pragma unroll
  for (int i = 0; i < 4; i++)
    vt[(size_t)(bx + ty + i * 8) * T_DIM + by + tx] = t[tx][ty + i * 8];
}

// ---------------------------------------------------------------------------
// Row softmax over [n_padd, row]; exp values held in registers (<=16/thread);
// writes P*2^14 fp16 once, bounded at the 128-aligned row-tile limit.
// ---------------------------------------------------------------------------
__global__ __launch_bounds__(256) void softmax_rows(const float* __restrict__ S,
                                                    __half* __restrict__ P,
                                                    const int* __restrict__ npad_p) {
  const int row = blockIdx.x;
  const int tid = threadIdx.x;
  const int npad = *npad_p;
  const float* rp = S + (size_t)row * T_DIM;
  __half* pp = P + (size_t)row * T_DIM;
  const int wend = ((row >> 7) + 1) << 7;  // GEMM3 read bound for this row
  __shared__ float red[8];
  if (row < npad) {
    for (int c = tid; c < wend; c += 256) pp[c] = __float2half(0.f);
    return;
  }
  const int lo = npad, hi = row;
  float m = -3.0e38f;
  for (int c = lo + tid; c <= hi; c += 256) m = fmaxf(m, rp[c]);
#pragma unroll
  for (int o = 16; o > 0; o >>= 1) m = fmaxf(m, __shfl_xor_sync(0xffffffffu, m, o));
  if ((tid & 31) == 0) red[tid >> 5] = m;
  __syncthreads();
  float bmax = red[0];
#pragma unroll
  for (int i = 1; i < 8; i++) bmax = fmaxf(bmax, red[i]);
  __syncthreads();

  float ev[16];
  float s = 0.f;
#pragma unroll
  for (int i = 0; i < 16; i++) {
    int c = lo + tid + i * 256;
    float e = (c <= hi) ? __expf(rp[c] - bmax) * 16384.0f : 0.f;  // *2^14 exact
    ev[i] = e;
    s += e;
  }
#pragma unroll
  for (int o = 16; o > 0; o >>= 1) s += __shfl_xor_sync(0xffffffffu, s, o);
  if ((tid & 31) == 0) red[tid >> 5] = s;
  __syncthreads();
  float bsum = 0.f;
#pragma unroll
  for (int i = 0; i < 8; i++) bsum += red[i];
  const float inv = 16384.0f / bsum;  // final P = e/bsum * 2^14

  for (int c = tid; c < lo; c += 256) pp[c] = __float2half(0.f);
#pragma unroll
  for (int i = 0; i < 16; i++) {
    int c = lo + tid + i * 256;
    if (c <= hi) pp[c] = __float2half_rn(ev[i] * inv);
  }
  for (int c = hi + 1 + tid; c < wend; c += 256) pp[c] = __float2half(0.f);
}

extern "C" void kernel_launch(void* const* d_in, const int* in_sizes, int n_in,
                              void* d_out, int out_size) {
  const float* x = (const float*)d_in[0];
  const float* W = (const float*)d_in[1];
  const float* bias = (const float*)d_in[2];
  const int* n_padd = (const int*)d_in[3];
  float* y = (float*)d_out;

  __half *qkv, *P, *vt, *xh, *wth;
  float* S;
  cudaGetSymbolAddress((void**)&qkv, g_qkv);
  cudaGetSymbolAddress((void**)&S, g_S);
  cudaGetSymbolAddress((void**)&P, g_P);
  cudaGetSymbolAddress((void**)&xh, g_xh);
  cudaGetSymbolAddress((void**)&wth, g_wth);
  cudaGetSymbolAddress((void**)&vt, g_vt);

  const float scale = 1.0f / sqrtf((float)NF_DIM);

  constexpr int SM_BYTES = NST * (BM * 64 + BN * 64);  // 98304

  cudaFuncSetAttribute((const void*)gemm_h<1, false, false>,
                       cudaFuncAttributeMaxDynamicSharedMemorySize, SM_BYTES);
  cudaFuncSetAttribute((const void*)gemm_h<0, true, false>,
                       cudaFuncAttributeMaxDynamicSharedMemorySize, SM_BYTES);
  cudaFuncSetAttribute((const void*)gemm_h<0, false, true>,
                       cudaFuncAttributeMaxDynamicSharedMemorySize, SM_BYTES);

  // Prep: x -> fp16 ; W -> W^T fp16
  conv_x<<<(T_DIM * C_DIM / 4 + 255) / 256, 256>>>(x, xh, T_DIM * C_DIM / 4);
  transpose_w<<<dim3(N3_DIM / 32, C_DIM / 32), 256>>>(W, wth);

  // GEMM1: qkv = x @ W + b   (single fp16 pass; writes fp16)
  gemm_h<1, false, false><<<dim3(N3_DIM / BN, T_DIM / BM), NTHR, SM_BYTES>>>(
      (const uint16_t*)xh, (const uint16_t*)wth, qkv, bias, 0.f,
      C_DIM, C_DIM, C_DIM, N3_DIM);

  // v^T
  transpose_v<<<dim3(NF_DIM / 32, T_DIM / 32), 256>>>(qkv, vt);

  // GEMM2: S = (q @ k^T) * scale   (causal block skip)
  gemm_h<0, true, false><<<dim3(T_DIM / BN, T_DIM / BM), NTHR, SM_BYTES>>>(
      (const uint16_t*)qkv, (const uint16_t*)(qkv + NF_DIM),
      S, nullptr, scale, NF_DIM, N3_DIM, N3_DIM, T_DIM);

  // Softmax -> P (fp16, *2^14, register-resident exp)
  softmax_rows<<<T_DIM, 256>>>(S, P, n_padd);

  // GEMM3: y = P @ v * 2^-14   (causal K bound)
  gemm_h<0, false, true><<<dim3(NF_DIM / BN, T_DIM / BM), NTHR, SM_BYTES>>>(
      (const uint16_t*)P, (const uint16_t*)vt,
      y, nullptr, 6.103515625e-05f, T_DIM, T_DIM, T_DIM, NF_DIM);
}

// round 11
// speedup vs baseline: 4.5093x; 1.2407x over previous
#include <cuda_runtime.h>
#include <cuda_fp16.h>
#include <math.h>
#include <cstdint>

#define T_DIM 4096
#define C_DIM 2048
#define NF_DIM 2048
#define N3_DIM 6144

constexpr int BM = 128, BN = 256, BK = 64;  // BK halves -> 128B smem rows
constexpr int NST = 3;                       // pipeline stages (48KB each)
constexpr int NTHR = 512;                    // 16 warps: 2(M) x 8(N) of 64x32

// Scratch (allocation-free rule: __device__ globals)
__device__ __half g_qkv[(size_t)T_DIM * N3_DIM];   // fp16 qkv (48 MB)
__device__ float g_S[(size_t)T_DIM * T_DIM];       // att logits (64 MB)
__device__ __half g_P[(size_t)T_DIM * T_DIM];      // P (fp16, *2^14)
__device__ __half g_xh[(size_t)T_DIM * C_DIM];     // x fp16
__device__ __half g_wth[(size_t)N3_DIM * C_DIM];   // W^T fp16
__device__ __half g_vt[(size_t)NF_DIM * T_DIM];    // v^T fp16

__device__ __forceinline__ void cpasync16(unsigned s, const void* g) {
  asm volatile("cp.async.cg.shared.global [%0], [%1], 16;\n" ::"r"(s), "l"(g));
}
__device__ __forceinline__ void cp_commit() { asm volatile("cp.async.commit_group;\n" ::); }
template <int N>
__device__ __forceinline__ void cp_wait() {
  asm volatile("cp.async.wait_group %0;\n" ::"n"(N));
}
__device__ __forceinline__ void ldsm4(uint32_t& r0, uint32_t& r1, uint32_t& r2,
                                      uint32_t& r3, unsigned addr) {
  asm volatile("ldmatrix.sync.aligned.m8n8.x4.shared.b16 {%0,%1,%2,%3}, [%4];"
               : "=r"(r0), "=r"(r1), "=r"(r2), "=r"(r3)
               : "r"(addr));
}
__device__ __forceinline__ void mma16(float (&c)[4], const uint32_t (&a)[4],
                                      const uint32_t (&b)[2]) {
  asm volatile(
      "mma.sync.aligned.m16n8k16.row.col.f32.f16.f16.f32 "
      "{%0,%1,%2,%3}, {%4,%5,%6,%7}, {%8,%9}, {%0,%1,%2,%3};\n"
      : "+f"(c[0]), "+f"(c[1]), "+f"(c[2]), "+f"(c[3])
      : "r"(a[0]), "r"(a[1]), "r"(a[2]), "r"(a[3]), "r"(b[0]), "r"(b[1]));
}

// ---------------------------------------------------------------------------
// fp16 NT GEMM: D[M,N] = A[M,K] @ B[N,K]^T   (fp32 accum)
// CTA 128x256, 16 warps of 64x32, BK=64 halves (128B rows, SW128 XOR swizzle),
// ldmatrix.x4 fragment loads, 3-stage cp.async pipeline.
// EPI: 0 -> float out * scale ; 1 -> half out + bias
// CSKIP: compact causal-triangle 1D launch (GEMM2)
// CK:    causal K bound + heavy-first row order (GEMM3)
// ---------------------------------------------------------------------------
template <int EPI, bool CSKIP, bool CK>
__global__ __launch_bounds__(NTHR, 1) void gemm_h(
    const uint16_t* __restrict__ A, const uint16_t* __restrict__ B,
    void* __restrict__ Dv, const float* __restrict__ bias, float scale,
    int K, int lda, int ldb, int ldd) {
  constexpr int ATB = BM * 128;  // 16 KB A tile
  constexpr int BTB = BN * 128;  // 32 KB B tile
  constexpr int STG = ATB + BTB;
  extern __shared__ __align__(16) char smem[];

  int r0, c0;
  if constexpr (CSKIP) {
    // triangular decode: row y (of BM) has y/2+1 col-blocks (of BN)
    int t = blockIdx.x;
    int s = (int)sqrtf((float)t);
    while ((s + 1) * (s + 1) <= t) s++;
    while (s * s > t) s--;
    int y, base;
    if (t >= s * (s + 1)) { y = 2 * s; base = s * (s + 1); }
    else                  { y = 2 * s - 1; base = s * s; }
    r0 = y * BM;
    c0 = (t - base) * BN;
  } else if constexpr (CK) {
    r0 = ((int)gridDim.y - 1 - (int)blockIdx.y) * BM;  // heavy rows first
    c0 = blockIdx.x * BN;
  } else {
    r0 = blockIdx.y * BM;
    c0 = blockIdx.x * BN;
  }
  const int kend = CK ? min(K, r0 + BM) : K;
  const int nk = kend / BK;

  const int tid = threadIdx.x, lane = tid & 31, warp = tid >> 5;
  const int wm = (warp >> 3) * 64, wn = (warp & 7) * 32;
  const unsigned sbase = (unsigned)__cvta_generic_to_shared(smem);

  auto sw_off = [](int r, int c) {
    return (unsigned)(r * 128 + ((c ^ (r & 7)) << 4));
  };
  auto load_stage = [&](int s, int kt) {
    unsigned b = sbase + s * STG;
#pragma unroll
    for (int i = 0; i < 2; i++) {  // A: 128 rows x 8 chunks = 1024
      int id = tid + i * NTHR, r = id >> 3, c = id & 7;
      cpasync16(b + sw_off(r, c), A + (size_t)(r0 + r) * lda + kt + c * 8);
    }
#pragma unroll
    for (int i = 0; i < 4; i++) {  // B: 256 rows x 8 chunks = 2048
      int id = tid + i * NTHR, r = id >> 3, c = id & 7;
      cpasync16(b + ATB + sw_off(r, c), B + (size_t)(c0 + r) * ldb + kt + c * 8);
    }
    cp_commit();
  };

  float acc[4][4][4];
#pragma unroll
  for (int i = 0; i < 4; i++)
#pragma unroll
    for (int j = 0; j < 4; j++)
#pragma unroll
      for (int r = 0; r < 4; r++) acc[i][j][r] = 0.f;

#pragma unroll
  for (int s = 0; s < NST - 1; s++) load_stage(s, s * BK);

  // --- per-thread ldmatrix address components ---
  // A x4: lanes 0-15 -> rows, lanes 16-31 -> same rows next 16B k-chunk
  const int cA = lane >> 4;
  unsigned aoff[4];
  int ax[4];
#pragma unroll
  for (int ma = 0; ma < 4; ma++) {
    int rowA = wm + ma * 16 + (lane & 15);
    aoff[ma] = (unsigned)(rowA * 128);
    ax[ma] = rowA & 7;
  }
  // B x4 (two n8 tiles per instr)
  const int cB = (lane >> 3) & 1;
  unsigned boff[2];
  int bx[2];
#pragma unroll
  for (int np = 0; np < 2; np++) {
    int rowB = wn + np * 16 + ((lane >> 4) * 8) + (lane & 7);
    boff[np] = (unsigned)(rowB * 128);
    bx[np] = rowB & 7;
  }

  for (int k = 0; k < nk; k++) {
    cp_wait<NST - 2>();
    __syncthreads();
    if (k + NST - 1 < nk) load_stage((k + NST - 1) % NST, (k + NST - 1) * BK);
    else cp_commit();  // keep group count consistent

    const unsigned sb = sbase + (unsigned)((k % NST) * STG);
    const unsigned sA = sb, sB = sb + ATB;

#pragma unroll
    for (int ks = 0; ks < 4; ks++) {
      const int kc0 = ks * 2;
      uint32_t ah[4][4], bh[4][2];
#pragma unroll
      for (int ma = 0; ma < 4; ma++)
        ldsm4(ah[ma][0], ah[ma][1], ah[ma][2], ah[ma][3],
              sA + aoff[ma] + (unsigned)(((kc0 + cA) ^ ax[ma]) << 4));
#pragma unroll
      for (int np = 0; np < 2; np++)
        ldsm4(bh[2 * np][0], bh[2 * np][1], bh[2 * np + 1][0], bh[2 * np + 1][1],
              sB + boff[np] + (unsigned)(((kc0 + cB) ^ bx[np]) << 4));
#pragma unroll
      for (int ma = 0; ma < 4; ma++)
#pragma unroll
        for (int na = 0; na < 4; na++) mma16(acc[ma][na], ah[ma], bh[na]);
    }
  }

  // ---- epilogue ----
  const int q = lane >> 2, t2 = lane & 3;
#pragma unroll
  for (int ma = 0; ma < 4; ma++) {
#pragma unroll
    for (int na = 0; na < 4; na++) {
      const int row = r0 + wm + ma * 16 + q;
      const int col = c0 + wn + na * 8 + t2 * 2;
      float v0 = acc[ma][na][0], v1 = acc[ma][na][1];
      float v2 = acc[ma][na][2], v3 = acc[ma][na][3];
      if constexpr (EPI == 1) {
        __half* D = (__half*)Dv;
        float b0 = bias[col], b1 = bias[col + 1];
        *(__half2*)(D + (size_t)row * ldd + col) = __floats2half2_rn(v0 + b0, v1 + b1);
        *(__half2*)(D + (size_t)(row + 8) * ldd + col) = __floats2half2_rn(v2 + b0, v3 + b1);
      } else {
        float* D = (float*)Dv;
        *(float2*)(D + (size_t)row * ldd + col) = make_float2(v0 * scale, v1 * scale);
        *(float2*)(D + (size_t)(row + 8) * ldd + col) = make_float2(v2 * scale, v3 * scale);
      }
    }
  }
}

// ---------------------------------------------------------------------------
// Prep kernels
// ---------------------------------------------------------------------------
__global__ __launch_bounds__(256) void conv_x(const float* __restrict__ in,
                                              __half* __restrict__ out, int n4) {
  int i = blockIdx.x * 256 + threadIdx.x;
  if (i >= n4) return;
  float4 v = ((const float4*)in)[i];
  __half2* op = (__half2*)(out + (size_t)i * 4);
  op[0] = __floats2half2_rn(v.x, v.y);
  op[1] = __floats2half2_rn(v.z, v.w);
}

// W [C, N3] float -> W^T [N3, C] fp16
__global__ __launch_bounds__(256) void transpose_w(const float* __restrict__ W,
                                                   __half* __restrict__ oh) {
  __shared__ float t[32][33];
  const int bx = blockIdx.x * 32, by = blockIdx.y * 32;
  const int tx = threadIdx.x & 31, ty = threadIdx.x >> 5;
#pragma unroll
  for (int i = 0; i < 4; i++)
    t[ty + i * 8][tx] = W[(size_t)(by + ty + i * 8) * N3_DIM + bx + tx];
  __syncthreads();
#pragma unroll
  for (int i = 0; i < 4; i++) {
    float v = t[tx][ty + i * 8];
    oh[(size_t)(bx + ty + i * 8) * C_DIM + by + tx] = __float2half_rn(v);
  }
}

// v (qkv cols [4096,6144)) half -> v^T [NF, T] half
__global__ __launch_bounds__(256) void transpose_v(const __half* __restrict__ qkv,
                                                   __half* __restrict__ vt) {
  __shared__ __half t[32][34];
  const int bx = blockIdx.x * 32, by = blockIdx.y * 32;
  const int tx = threadIdx.x & 31, ty = threadIdx.x >> 5;
#pragma unroll
  for (int i = 0; i < 4; i++)
    t[ty + i * 8][tx] = qkv[(size_t)(by + ty + i * 8) * N3_DIM + 2 * NF_DIM + bx + tx];
  __syncthreads();
#pragma unroll
  for (int i = 0; i < 4; i++)
    vt[(size_t)(bx + ty + i * 8) * T_DIM + by + tx] = t[tx][ty + i * 8];
}

// ---------------------------------------------------------------------------
// Row softmax over [n_padd, row]; heavy rows scheduled first; exp in regs;
// writes P*2^14 fp16 once, bounded at the 128-aligned row-tile limit.
// ---------------------------------------------------------------------------
__global__ __launch_bounds__(256) void softmax_rows(const float* __restrict__ S,
                                                    __half* __restrict__ P,
                                                    const int* __restrict__ npad_p) {
  const int row = (int)gridDim.x - 1 - (int)blockIdx.x;  // longest rows first
  const int tid = threadIdx.x;
  const int npad = *npad_p;
  const float* rp = S + (size_t)row * T_DIM;
  __half* pp = P + (size_t)row * T_DIM;
  const int wend = ((row >> 7) + 1) << 7;  // GEMM3 read bound for this row
  __shared__ float red[8];
  if (row < npad) {
    for (int c = tid; c < wend; c += 256) pp[c] = __float2half(0.f);
    return;
  }
  const int lo = npad, hi = row;
  float m = -3.0e38f;
  for (int c = lo + tid; c <= hi; c += 256) m = fmaxf(m, rp[c]);
#pragma unroll
  for (int o = 16; o > 0; o >>= 1) m = fmaxf(m, __shfl_xor_sync(0xffffffffu, m, o));
  if ((tid & 31) == 0) red[tid >> 5] = m;
  __syncthreads();
  float bmax = red[0];
#pragma unroll
  for (int i = 1; i < 8; i++) bmax = fmaxf(bmax, red[i]);
  __syncthreads();

  float ev[16];
  float s = 0.f;
#pragma unroll
  for (int i = 0; i < 16; i++) {
    int c = lo + tid + i * 256;
    float e = (c <= hi) ? __expf(rp[c] - bmax) * 16384.0f : 0.f;  // *2^14 exact
    ev[i] = e;
    s += e;
  }
#pragma unroll
  for (int o = 16; o > 0; o >>= 1) s += __shfl_xor_sync(0xffffffffu, s, o);
  if ((tid & 31) == 0) red[tid >> 5] = s;
  __syncthreads();
  float bsum = 0.f;
#pragma unroll
  for (int i = 0; i < 8; i++) bsum += red[i];
  const float inv = 16384.0f / bsum;  // final P = e/bsum * 2^14

  for (int c = tid; c < lo; c += 256) pp[c] = __float2half(0.f);
#pragma unroll
  for (int i = 0; i < 16; i++) {
    int c = lo + tid + i * 256;
    if (c <= hi) pp[c] = __float2half_rn(ev[i] * inv);
  }
  for (int c = hi + 1 + tid; c < wend; c += 256) pp[c] = __float2half(0.f);
}

extern "C" void kernel_launch(void* const* d_in, const int* in_sizes, int n_in,
                              void* d_out, int out_size) {
  const float* x = (const float*)d_in[0];
  const float* W = (const float*)d_in[1];
  const float* bias = (const float*)d_in[2];
  const int* n_padd = (const int*)d_in[3];
  float* y = (float*)d_out;

  __half *qkv, *P, *vt, *xh, *wth;
  float* S;
  cudaGetSymbolAddress((void**)&qkv, g_qkv);
  cudaGetSymbolAddress((void**)&S, g_S);
  cudaGetSymbolAddress((void**)&P, g_P);
  cudaGetSymbolAddress((void**)&xh, g_xh);
  cudaGetSymbolAddress((void**)&wth, g_wth);
  cudaGetSymbolAddress((void**)&vt, g_vt);

  const float scale = 1.0f / sqrtf((float)NF_DIM);

  constexpr int SM_BYTES = NST * (BM * 128 + BN * 128);  // 147456

  cudaFuncSetAttribute((const void*)gemm_h<1, false, false>,
                       cudaFuncAttributeMaxDynamicSharedMemorySize, SM_BYTES);
  cudaFuncSetAttribute((const void*)gemm_h<0, true, false>,
                       cudaFuncAttributeMaxDynamicSharedMemorySize, SM_BYTES);
  cudaFuncSetAttribute((const void*)gemm_h<0, false, true>,
                       cudaFuncAttributeMaxDynamicSharedMemorySize, SM_BYTES);

  // Prep: x -> fp16 ; W -> W^T fp16
  conv_x<<<(T_DIM * C_DIM / 4 + 255) / 256, 256>>>(x, xh, T_DIM * C_DIM / 4);
  transpose_w<<<dim3(N3_DIM / 32, C_DIM / 32), 256>>>(W, wth);

  // GEMM1: qkv = x @ W + b   (single fp16 pass; writes fp16)
  gemm_h<1, false, false><<<dim3(N3_DIM / BN, T_DIM / BM), NTHR, SM_BYTES>>>(
      (const uint16_t*)xh, (const uint16_t*)wth, qkv, bias, 0.f,
      C_DIM, C_DIM, C_DIM, N3_DIM);

  // v^T
  transpose_v<<<dim3(NF_DIM / 32, T_DIM / 32), 256>>>(qkv, vt);

  // GEMM2: S = (q @ k^T) * scale   (compact causal triangle: 272 CTAs)
  gemm_h<0, true, false><<<272, NTHR, SM_BYTES>>>(
      (const uint16_t*)qkv, (const uint16_t*)(qkv + NF_DIM),
      S, nullptr, scale, NF_DIM, N3_DIM, N3_DIM, T_DIM);

  // Softmax -> P (fp16, *2^14, register-resident exp, heavy-first)
  softmax_rows<<<T_DIM, 256>>>(S, P, n_padd);

  // GEMM3: y = P @ v * 2^-14   (causal K bound, heavy-first rows)
  gemm_h<0, false, true><<<dim3(NF_DIM / BN, T_DIM / BM), NTHR, SM_BYTES>>>(
      (const uint16_t*)P, (const uint16_t*)vt,
      y, nullptr, 6.103515625e-05f, T_DIM, T_DIM, T_DIM, NF_DIM);
}

// round 13
// speedup vs baseline: 4.5958x; 1.0192x over previous
#include <cuda_runtime.h>
#include <cuda_fp16.h>
#include <math.h>
#include <cstdint>

#define T_DIM 4096
#define C_DIM 2048
#define NF_DIM 2048
#define N3_DIM 6144

constexpr int BM = 128, BN = 256, BK = 64;  // BK halves -> 128B smem rows (NT)
constexpr int NST = 3;                       // pipeline stages (48KB each)
constexpr int NTHR = 512;                    // 16 warps: 2(M) x 8(N) of 64x32

// Scratch (allocation-free rule: __device__ globals)
__device__ __half g_qkv[(size_t)T_DIM * N3_DIM];   // fp16 qkv (48 MB)
__device__ float g_S[(size_t)T_DIM * T_DIM];       // att logits (64 MB)
__device__ __half g_P[(size_t)T_DIM * T_DIM];      // P (fp16, *2^14)
__device__ __half g_xh[(size_t)T_DIM * C_DIM];     // x fp16
__device__ __half g_wth[(size_t)N3_DIM * C_DIM];   // W^T fp16
__device__ uint32_t g_rowmax[T_DIM];               // monotonic-uint row maxima

__device__ __forceinline__ uint32_t fmap(float f) {  // order-preserving f32->u32
  uint32_t u = __float_as_uint(f);
  return (u & 0x80000000u) ? ~u : (u | 0x80000000u);
}
__device__ __forceinline__ float funmap(uint32_t u) {
  return __uint_as_float((u & 0x80000000u) ? (u & 0x7FFFFFFFu) : ~u);
}

__device__ __forceinline__ void cpasync16(unsigned s, const void* g) {
  asm volatile("cp.async.cg.shared.global [%0], [%1], 16;\n" ::"r"(s), "l"(g));
}
__device__ __forceinline__ void cp_commit() { asm volatile("cp.async.commit_group;\n" ::); }
template <int N>
__device__ __forceinline__ void cp_wait() {
  asm volatile("cp.async.wait_group %0;\n" ::"n"(N));
}
__device__ __forceinline__ void ldsm4(uint32_t& r0, uint32_t& r1, uint32_t& r2,
                                      uint32_t& r3, unsigned addr) {
  asm volatile("ldmatrix.sync.aligned.m8n8.x4.shared.b16 {%0,%1,%2,%3}, [%4];"
               : "=r"(r0), "=r"(r1), "=r"(r2), "=r"(r3)
               : "r"(addr));
}
__device__ __forceinline__ void ldsm4t(uint32_t& r0, uint32_t& r1, uint32_t& r2,
                                       uint32_t& r3, unsigned addr) {
  asm volatile("ldmatrix.sync.aligned.m8n8.x4.trans.shared.b16 {%0,%1,%2,%3}, [%4];"
               : "=r"(r0), "=r"(r1), "=r"(r2), "=r"(r3)
               : "r"(addr));
}
__device__ __forceinline__ void mma16(float (&c)[4], const uint32_t (&a)[4],
                                      const uint32_t (&b)[2]) {
  asm volatile(
      "mma.sync.aligned.m16n8k16.row.col.f32.f16.f16.f32 "
      "{%0,%1,%2,%3}, {%4,%5,%6,%7}, {%8,%9}, {%0,%1,%2,%3};\n"
      : "+f"(c[0]), "+f"(c[1]), "+f"(c[2]), "+f"(c[3])
      : "r"(a[0]), "r"(a[1]), "r"(a[2]), "r"(a[3]), "r"(b[0]), "r"(b[1]));
}

// ---------------------------------------------------------------------------
// fp16 GEMM: D[M,N] = A[M,K] @ op(B)   (fp32 accum)
// A K-major. BNN=0: B[N,K] K-major (NT, ldmatrix). BNN=1: B[K,N] row-major
// (NN, ldmatrix.trans; tile = BK rows x 512B swizzled).
// EPI: 0 -> float out * scale ; 1 -> half out + bias
// CSKIP: compact causal-triangle 1D launch + row-max side output (GEMM2)
// CK:    causal K bound + heavy-first row order (GEMM3)
// ---------------------------------------------------------------------------
template <int EPI, bool CSKIP, bool CK, bool BNN>
__global__ __launch_bounds__(NTHR, 1) void gemm_h(
    const uint16_t* __restrict__ A, const uint16_t* __restrict__ B,
    void* __restrict__ Dv, const float* __restrict__ bias, float scale,
    int K, int lda, int ldb, int ldd) {
  constexpr int ATB = BM * 128;  // 16 KB A tile
  constexpr int BTB = BN * 128;  // 32 KB B tile (NT: 256x128B, NN: 64x512B)
  constexpr int STG = ATB + BTB;
  extern __shared__ __align__(16) char smem[];
  __shared__ uint32_t smax[BM];

  int r0, c0;
  if constexpr (CSKIP) {
    // triangular decode: row y (of BM) has y/2+1 col-blocks (of BN)
    int t = blockIdx.x;
    int s = (int)sqrtf((float)t);
    while ((s + 1) * (s + 1) <= t) s++;
    while (s * s > t) s--;
    int y, base;
    if (t >= s * (s + 1)) { y = 2 * s; base = s * (s + 1); }
    else                  { y = 2 * s - 1; base = s * s; }
    r0 = y * BM;
    c0 = (t - base) * BN;
  } else if constexpr (CK) {
    r0 = ((int)gridDim.y - 1 - (int)blockIdx.y) * BM;  // heavy rows first
    c0 = blockIdx.x * BN;
  } else {
    r0 = blockIdx.y * BM;
    c0 = blockIdx.x * BN;
  }
  const int kend = CK ? min(K, r0 + BM) : K;
  const int nk = kend / BK;

  const int tid = threadIdx.x, lane = tid & 31, warp = tid >> 5;
  const int wm = (warp >> 3) * 64, wn = (warp & 7) * 32;
  const unsigned sbase = (unsigned)__cvta_generic_to_shared(smem);

  if constexpr (CSKIP) {
    if (tid < BM) smax[tid] = 0u;
  }

  auto sw_off = [](int r, int c) {  // 128B-row XOR swizzle (A, B-NT)
    return (unsigned)(r * 128 + ((c ^ (r & 7)) << 4));
  };
  auto load_stage = [&](int s, int kt) {
    unsigned b = sbase + s * STG;
#pragma unroll
    for (int i = 0; i < 2; i++) {  // A: 128 rows x 8 chunks = 1024
      int id = tid + i * NTHR, r = id >> 3, c = id & 7;
      cpasync16(b + sw_off(r, c), A + (size_t)(r0 + r) * lda + kt + c * 8);
    }
    if constexpr (BNN) {
#pragma unroll
      for (int i = 0; i < 4; i++) {  // B: 64 rows x 32 chunks = 2048
        int id = tid + i * NTHR, r = id >> 5, c = id & 31;
        cpasync16(b + ATB + (unsigned)(r * 512 + ((c ^ (r & 7)) << 4)),
                  B + (size_t)(kt + r) * ldb + c0 + c * 8);
      }
    } else {
#pragma unroll
      for (int i = 0; i < 4; i++) {  // B: 256 rows x 8 chunks = 2048
        int id = tid + i * NTHR, r = id >> 3, c = id & 7;
        cpasync16(b + ATB + sw_off(r, c), B + (size_t)(c0 + r) * ldb + kt + c * 8);
      }
    }
    cp_commit();
  };

  float acc[4][4][4];
#pragma unroll
  for (int i = 0; i < 4; i++)
#pragma unroll
    for (int j = 0; j < 4; j++)
#pragma unroll
      for (int r = 0; r < 4; r++) acc[i][j][r] = 0.f;

#pragma unroll
  for (int s = 0; s < NST - 1; s++) load_stage(s, s * BK);

  // --- per-thread ldmatrix address components ---
  const int cA = lane >> 4;
  unsigned aoff[4];
  int ax[4];
#pragma unroll
  for (int ma = 0; ma < 4; ma++) {
    int rowA = wm + ma * 16 + (lane & 15);
    aoff[ma] = (unsigned)(rowA * 128);
    ax[ma] = rowA & 7;
  }
  // B-NT components
  const int cB = (lane >> 3) & 1;
  unsigned boff[2];
  int bx[2];
#pragma unroll
  for (int np = 0; np < 2; np++) {
    int rowB = wn + np * 16 + ((lane >> 4) * 8) + (lane & 7);
    boff[np] = (unsigned)(rowB * 128);
    bx[np] = rowB & 7;
  }
  // B-NN components: row = ks*16 + rnn ; chunk cb ^ (lane&7)
  const int rnn = (lane & 7) + (((lane >> 3) & 1) << 3);
  unsigned bchunk[2];
#pragma unroll
  for (int np = 0; np < 2; np++) {
    int cb = (wn >> 3) + np * 2 + (lane >> 4);
    bchunk[np] = (unsigned)((cb ^ (lane & 7)) << 4);
  }

  for (int k = 0; k < nk; k++) {
    cp_wait<NST - 2>();
    __syncthreads();
    if (k + NST - 1 < nk) load_stage((k + NST - 1) % NST, (k + NST - 1) * BK);
    else cp_commit();  // keep group count consistent

    const unsigned sb = sbase + (unsigned)((k % NST) * STG);
    const unsigned sA = sb, sB = sb + ATB;

#pragma unroll
    for (int ks = 0; ks < 4; ks++) {
      const int kc0 = ks * 2;
      uint32_t ah[4][4], bh[4][2];
#pragma unroll
      for (int ma = 0; ma < 4; ma++)
        ldsm4(ah[ma][0], ah[ma][1], ah[ma][2], ah[ma][3],
              sA + aoff[ma] + (unsigned)(((kc0 + cA) ^ ax[ma]) << 4));
      if constexpr (BNN) {
        const unsigned rowbyte = (unsigned)((ks * 16 + rnn) * 512);
#pragma unroll
        for (int np = 0; np < 2; np++)
          ldsm4t(bh[2 * np][0], bh[2 * np][1], bh[2 * np + 1][0], bh[2 * np + 1][1],
                 sB + rowbyte + bchunk[np]);
      } else {
#pragma unroll
        for (int np = 0; np < 2; np++)
          ldsm4(bh[2 * np][0], bh[2 * np][1], bh[2 * np + 1][0], bh[2 * np + 1][1],
                sB + boff[np] + (unsigned)(((kc0 + cB) ^ bx[np]) << 4));
      }
#pragma unroll
      for (int ma = 0; ma < 4; ma++)
#pragma unroll
        for (int na = 0; na < 4; na++) mma16(acc[ma][na], ah[ma], bh[na]);
    }
  }

  // ---- epilogue ----
  const int q = lane >> 2, t2 = lane & 3;
  if constexpr (CSKIP) __syncthreads();  // smax init visible
#pragma unroll
  for (int ma = 0; ma < 4; ma++) {
    float m0 = -3.0e38f, m1 = -3.0e38f;
#pragma unroll
    for (int na = 0; na < 4; na++) {
      const int row = r0 + wm + ma * 16 + q;
      const int col = c0 + wn + na * 8 + t2 * 2;
      float v0 = acc[ma][na][0], v1 = acc[ma][na][1];
      float v2 = acc[ma][na][2], v3 = acc[ma][na][3];
      if constexpr (EPI == 1) {
        __half* D = (__half*)Dv;
        float b0 = bias[col], b1 = bias[col + 1];
        *(__half2*)(D + (size_t)row * ldd + col) = __floats2half2_rn(v0 + b0, v1 + b1);
        *(__half2*)(D + (size_t)(row + 8) * ldd + col) = __floats2half2_rn(v2 + b0, v3 + b1);
      } else {
        float* D = (float*)Dv;
        v0 *= scale; v1 *= scale; v2 *= scale; v3 *= scale;
        *(float2*)(D + (size_t)row * ldd + col) = make_float2(v0, v1);
        *(float2*)(D + (size_t)(row + 8) * ldd + col) = make_float2(v2, v3);
        if constexpr (CSKIP) {
          m0 = fmaxf(m0, fmaxf(v0, v1));
          m1 = fmaxf(m1, fmaxf(v2, v3));
        }
      }
    }
    if constexpr (CSKIP) {
      m0 = fmaxf(m0, __shfl_xor_sync(0xffffffffu, m0, 1));
      m0 = fmaxf(m0, __shfl_xor_sync(0xffffffffu, m0, 2));
      m1 = fmaxf(m1, __shfl_xor_sync(0xffffffffu, m1, 1));
      m1 = fmaxf(m1, __shfl_xor_sync(0xffffffffu, m1, 2));
      if (t2 == 0) {
        atomicMax(&smax[wm + ma * 16 + q], fmap(m0));
        atomicMax(&smax[wm + ma * 16 + q + 8], fmap(m1));
      }
    }
  }
  if constexpr (CSKIP) {
    __syncthreads();
    if (tid < BM) atomicMax(&g_rowmax[r0 + tid], smax[tid]);
  }
}

// ---------------------------------------------------------------------------
// Prep kernels
// ---------------------------------------------------------------------------
__global__ __launch_bounds__(256) void conv_x(const float* __restrict__ in,
                                              __half* __restrict__ out, int n4) {
  int i = blockIdx.x * 256 + threadIdx.x;
  if (i < T_DIM) g_rowmax[i] = 0u;  // re-init row maxima every call
  if (i >= n4) return;
  float4 v = ((const float4*)in)[i];
  __half2* op = (__half2*)(out + (size_t)i * 4);
  op[0] = __floats2half2_rn(v.x, v.y);
  op[1] = __floats2half2_rn(v.z, v.w);
}

// W [C, N3] float -> W^T [N3, C] fp16
__global__ __launch_bounds__(256) void transpose_w(const float* __restrict__ W,
                                                   __half* __restrict__ oh) {
  __shared__ float t[32][33];
  const int bx = blockIdx.x * 32, by = blockIdx.y * 32;
  const int tx = threadIdx.x & 31, ty = threadIdx.x >> 5;
#pragma unroll
  for (int i = 0; i < 4; i++)
    t[ty + i * 8][tx] = W[(size_t)(by + ty + i * 8) * N3_DIM + bx + tx];
  __syncthreads();
#pragma unroll
  for (int i = 0; i < 4; i++) {
    float v = t[tx][ty + i * 8];
    oh[(size_t)(bx + ty + i * 8) * C_DIM + by + tx] = __float2half_rn(v);
  }
}

// ---------------------------------------------------------------------------
// Row softmax over [n_padd, row]; single S pass using precomputed row max
// (superset max — exactly cancelled by normalization). Writes P*2^14 fp16,
// bounded at the 128-aligned row-tile limit. Heavy rows first.
// ---------------------------------------------------------------------------
__global__ __launch_bounds__(256) void softmax_rows(const float* __restrict__ S,
                                                    __half* __restrict__ P,
                                                    const int* __restrict__ npad_p) {
  const int row = (int)gridDim.x - 1 - (int)blockIdx.x;  // longest rows first
  const int tid = threadIdx.x;
  const int npad = *npad_p;
  const float* rp = S + (size_t)row * T_DIM;
  __half* pp = P + (size_t)row * T_DIM;
  const int wend = ((row >> 7) + 1) << 7;  // GEMM3 read bound for this row
  __shared__ float red[8];
  if (row < npad) {
    for (int c = tid; c < wend; c += 256) pp[c] = __float2half(0.f);
    return;
  }
  const int lo = npad, hi = row;
  const float bmax = funmap(g_rowmax[row]);

  float ev[16];
  float s = 0.f;
#pragma unroll
  for (int i = 0; i < 16; i++) {
    int c = lo + tid + i * 256;
    float e = (c <= hi) ? __expf(rp[c] - bmax) * 16384.0f : 0.f;  // *2^14 exact
    ev[i] = e;
    s += e;
  }
#pragma unroll
  for (int o = 16; o > 0; o >>= 1) s += __shfl_xor_sync(0xffffffffu, s, o);
  if ((tid & 31) == 0) red[tid >> 5] = s;
  __syncthreads();
  float bsum = 0.f;
#pragma unroll
  for (int i = 0; i < 8; i++) bsum += red[i];
  const float inv = 16384.0f / bsum;  // final P = e/bsum * 2^14

  for (int c = tid; c < lo; c += 256) pp[c] = __float2half(0.f);
#pragma unroll
  for (int i = 0; i < 16; i++) {
    int c = lo + tid + i * 256;
    if (c <= hi) pp[c] = __float2half_rn(ev[i] * inv);
  }
  for (int c = hi + 1 + tid; c < wend; c += 256) pp[c] = __float2half(0.f);
}

extern "C" void kernel_launch(void* const* d_in, const int* in_sizes, int n_in,
                              void* d_out, int out_size) {
  const float* x = (const float*)d_in[0];
  const float* W = (const float*)d_in[1];
  const float* bias = (const float*)d_in[2];
  const int* n_padd = (const int*)d_in[3];
  float* y = (float*)d_out;

  __half *qkv, *P, *xh, *wth;
  float* S;
  cudaGetSymbolAddress((void**)&qkv, g_qkv);
  cudaGetSymbolAddress((void**)&S, g_S);
  cudaGetSymbolAddress((void**)&P, g_P);
  cudaGetSymbolAddress((void**)&xh, g_xh);
  cudaGetSymbolAddress((void**)&wth, g_wth);

  const float scale = 1.0f / sqrtf((float)NF_DIM);

  constexpr int SM_BYTES = NST * (BM * 128 + BN * 128);  // 147456

  cudaFuncSetAttribute((const void*)gemm_h<1, false, false, false>,
                       cudaFuncAttributeMaxDynamicSharedMemorySize, SM_BYTES);
  cudaFuncSetAttribute((const void*)gemm_h<0, true, false, false>,
                       cudaFuncAttributeMaxDynamicSharedMemorySize, SM_BYTES);
  cudaFuncSetAttribute((const void*)gemm_h<0, false, true, true>,
                       cudaFuncAttributeMaxDynamicSharedMemorySize, SM_BYTES);

  // Prep: x -> fp16 (+rowmax init) ; W -> W^T fp16
  conv_x<<<(T_DIM * C_DIM / 4 + 255) / 256, 256>>>(x, xh, T_DIM * C_DIM / 4);
  transpose_w<<<dim3(N3_DIM / 32, C_DIM / 32), 256>>>(W, wth);

  // GEMM1: qkv = x @ W + b   (NT; writes fp16)
  gemm_h<1, false, false, false><<<dim3(N3_DIM / BN, T_DIM / BM), NTHR, SM_BYTES>>>(
      (const uint16_t*)xh, (const uint16_t*)wth, qkv, bias, 0.f,
      C_DIM, C_DIM, C_DIM, N3_DIM);

  // GEMM2: S = (q @ k^T) * scale   (NT triangle, 272 CTAs; emits row maxima)
  gemm_h<0, true, false, false><<<272, NTHR, SM_BYTES>>>(
      (const uint16_t*)qkv, (const uint16_t*)(qkv + NF_DIM),
      S, nullptr, scale, NF_DIM, N3_DIM, N3_DIM, T_DIM);

  // Softmax -> P (fp16, *2^14, single pass using precomputed max)
  softmax_rows<<<T_DIM, 256>>>(S, P, n_padd);

  // GEMM3: y = P @ v * 2^-14   (A=P K-major; B=v NN direct from qkv)
  gemm_h<0, false, true, true><<<dim3(NF_DIM / BN, T_DIM / BM), NTHR, SM_BYTES>>>(
      (const uint16_t*)P, (const uint16_t*)(qkv + 2 * NF_DIM),
      y, nullptr, 6.103515625e-05f, T_DIM, T_DIM, N3_DIM, NF_DIM);
}

// round 14
// speedup vs baseline: 4.9229x; 1.0712x over previous
#include <cuda_runtime.h>
#include <cuda_fp16.h>
#include <math.h>
#include <cstdint>

#define T_DIM 4096
#define C_DIM 2048
#define NF_DIM 2048
#define N3_DIM 6144

constexpr int BM = 128, BN = 128, BK = 64;  // BK halves -> 128B smem rows (NT)
constexpr int NST = 3;                       // pipeline stages (32KB each)
constexpr int NTHR = 256;                    // 8 warps: 2(M) x 4(N) of 64x32

// Scratch (allocation-free rule: __device__ globals)
__device__ __half g_qkv[(size_t)T_DIM * N3_DIM];   // fp16 qkv (48 MB)
__device__ float g_S[(size_t)T_DIM * T_DIM];       // att logits (64 MB)
__device__ __half g_P[(size_t)T_DIM * T_DIM];      // P (fp16, *2^14)
__device__ __half g_xh[(size_t)T_DIM * C_DIM];     // x fp16
__device__ __half g_wth[(size_t)N3_DIM * C_DIM];   // W^T fp16
__device__ uint32_t g_rowmax[T_DIM];               // monotonic-uint row maxima

__device__ __forceinline__ uint32_t fmap(float f) {  // order-preserving f32->u32
  uint32_t u = __float_as_uint(f);
  return (u & 0x80000000u) ? ~u : (u | 0x80000000u);
}
__device__ __forceinline__ float funmap(uint32_t u) {
  return __uint_as_float((u & 0x80000000u) ? (u & 0x7FFFFFFFu) : ~u);
}

__device__ __forceinline__ void cpasync16(unsigned s, const void* g) {
  asm volatile("cp.async.cg.shared.global [%0], [%1], 16;\n" ::"r"(s), "l"(g));
}
__device__ __forceinline__ void cp_commit() { asm volatile("cp.async.commit_group;\n" ::); }
template <int N>
__device__ __forceinline__ void cp_wait() {
  asm volatile("cp.async.wait_group %0;\n" ::"n"(N));
}
__device__ __forceinline__ void ldsm4(uint32_t& r0, uint32_t& r1, uint32_t& r2,
                                      uint32_t& r3, unsigned addr) {
  asm volatile("ldmatrix.sync.aligned.m8n8.x4.shared.b16 {%0,%1,%2,%3}, [%4];"
               : "=r"(r0), "=r"(r1), "=r"(r2), "=r"(r3)
               : "r"(addr));
}
__device__ __forceinline__ void ldsm4t(uint32_t& r0, uint32_t& r1, uint32_t& r2,
                                       uint32_t& r3, unsigned addr) {
  asm volatile("ldmatrix.sync.aligned.m8n8.x4.trans.shared.b16 {%0,%1,%2,%3}, [%4];"
               : "=r"(r0), "=r"(r1), "=r"(r2), "=r"(r3)
               : "r"(addr));
}
__device__ __forceinline__ void mma16(float (&c)[4], const uint32_t (&a)[4],
                                      const uint32_t (&b)[2]) {
  asm volatile(
      "mma.sync.aligned.m16n8k16.row.col.f32.f16.f16.f32 "
      "{%0,%1,%2,%3}, {%4,%5,%6,%7}, {%8,%9}, {%0,%1,%2,%3};\n"
      : "+f"(c[0]), "+f"(c[1]), "+f"(c[2]), "+f"(c[3])
      : "r"(a[0]), "r"(a[1]), "r"(a[2]), "r"(a[3]), "r"(b[0]), "r"(b[1]));
}

// ---------------------------------------------------------------------------
// fp16 GEMM: D[M,N] = A[M,K] @ op(B)   (fp32 accum)
// CTA 128x128, 2 CTAs/SM (256 thr, 8 warps of 64x32), BK=64, 3-stage cp.async.
// A K-major. BNN=0: B[N,K] K-major (NT, ldmatrix). BNN=1: B[K,N] row-major
// (NN, ldmatrix.trans; tile = BK rows x 256B swizzled).
// EPI: 0 -> float out * scale ; 1 -> half out + bias
// CSKIP: compact causal-triangle 1D launch + row-max side output (GEMM2)
// CK:    causal K bound + heavy-first row order (GEMM3)
// ---------------------------------------------------------------------------
template <int EPI, bool CSKIP, bool CK, bool BNN>
__global__ __launch_bounds__(NTHR, 2) void gemm_h(
    const uint16_t* __restrict__ A, const uint16_t* __restrict__ B,
    void* __restrict__ Dv, const float* __restrict__ bias, float scale,
    int K, int lda, int ldb, int ldd) {
  constexpr int ATB = BM * 128;  // 16 KB A tile
  constexpr int BTB = BN * 128;  // 16 KB B tile (NT: 128x128B, NN: 64x256B)
  constexpr int STG = ATB + BTB;
  extern __shared__ __align__(16) char smem[];
  __shared__ uint32_t smax[BM];

  int r0, c0;
  if constexpr (CSKIP) {
    // triangular decode: row y has y+1 col-blocks; t = y(y+1)/2 + c
    int t = blockIdx.x;
    int y = (int)((sqrtf(8.f * (float)t + 1.f) - 1.f) * 0.5f);
    while ((y + 1) * (y + 2) / 2 <= t) y++;
    while (y * (y + 1) / 2 > t) y--;
    r0 = y * BM;
    c0 = (t - y * (y + 1) / 2) * BN;
  } else if constexpr (CK) {
    r0 = ((int)gridDim.y - 1 - (int)blockIdx.y) * BM;  // heavy rows first
    c0 = blockIdx.x * BN;
  } else {
    r0 = blockIdx.y * BM;
    c0 = blockIdx.x * BN;
  }
  const int kend = CK ? min(K, r0 + BM) : K;
  const int nk = kend / BK;

  const int tid = threadIdx.x, lane = tid & 31, warp = tid >> 5;
  const int wm = (warp >> 2) * 64, wn = (warp & 3) * 32;
  const unsigned sbase = (unsigned)__cvta_generic_to_shared(smem);

  if constexpr (CSKIP) {
    if (tid < BM) smax[tid] = 0u;
  }

  auto sw_off = [](int r, int c) {  // 128B-row XOR swizzle (A, B-NT)
    return (unsigned)(r * 128 + ((c ^ (r & 7)) << 4));
  };
  auto load_stage = [&](int s, int kt) {
    unsigned b = sbase + s * STG;
#pragma unroll
    for (int i = 0; i < 4; i++) {  // A: 128 rows x 8 chunks = 1024
      int id = tid + i * NTHR, r = id >> 3, c = id & 7;
      cpasync16(b + sw_off(r, c), A + (size_t)(r0 + r) * lda + kt + c * 8);
    }
    if constexpr (BNN) {
#pragma unroll
      for (int i = 0; i < 4; i++) {  // B: 64 rows x 16 chunks = 1024
        int id = tid + i * NTHR, r = id >> 4, c = id & 15;
        cpasync16(b + ATB + (unsigned)(r * 256 + ((c ^ (r & 7)) << 4)),
                  B + (size_t)(kt + r) * ldb + c0 + c * 8);
      }
    } else {
#pragma unroll
      for (int i = 0; i < 4; i++) {  // B: 128 rows x 8 chunks = 1024
        int id = tid + i * NTHR, r = id >> 3, c = id & 7;
        cpasync16(b + ATB + sw_off(r, c), B + (size_t)(c0 + r) * ldb + kt + c * 8);
      }
    }
    cp_commit();
  };

  float acc[4][4][4];
#pragma unroll
  for (int i = 0; i < 4; i++)
#pragma unroll
    for (int j = 0; j < 4; j++)
#pragma unroll
      for (int r = 0; r < 4; r++) acc[i][j][r] = 0.f;

#pragma unroll
  for (int s = 0; s < NST - 1; s++) load_stage(s, s * BK);

  // --- per-thread ldmatrix address components ---
  const int cA = lane >> 4;
  unsigned aoff[4];
  int ax[4];
#pragma unroll
  for (int ma = 0; ma < 4; ma++) {
    int rowA = wm + ma * 16 + (lane & 15);
    aoff[ma] = (unsigned)(rowA * 128);
    ax[ma] = rowA & 7;
  }
  // B-NT components
  const int cB = (lane >> 3) & 1;
  unsigned boff[2];
  int bx[2];
#pragma unroll
  for (int np = 0; np < 2; np++) {
    int rowB = wn + np * 16 + ((lane >> 4) * 8) + (lane & 7);
    boff[np] = (unsigned)(rowB * 128);
    bx[np] = rowB & 7;
  }
  // B-NN components: row = ks*16 + rnn ; chunk cb ^ (lane&7); 256B rows
  const int rnn = (lane & 7) + (((lane >> 3) & 1) << 3);
  unsigned bchunk[2];
#pragma unroll
  for (int np = 0; np < 2; np++) {
    int cb = (wn >> 3) + np * 2 + (lane >> 4);  // 0..15
    bchunk[np] = (unsigned)((cb ^ (lane & 7)) << 4);
  }

  for (int k = 0; k < nk; k++) {
    cp_wait<NST - 2>();
    __syncthreads();
    if (k + NST - 1 < nk) load_stage((k + NST - 1) % NST, (k + NST - 1) * BK);
    else cp_commit();  // keep group count consistent

    const unsigned sb = sbase + (unsigned)((k % NST) * STG);
    const unsigned sA = sb, sB = sb + ATB;

#pragma unroll
    for (int ks = 0; ks < 4; ks++) {
      const int kc0 = ks * 2;
      uint32_t ah[4][4], bh[4][2];
#pragma unroll
      for (int ma = 0; ma < 4; ma++)
        ldsm4(ah[ma][0], ah[ma][1], ah[ma][2], ah[ma][3],
              sA + aoff[ma] + (unsigned)(((kc0 + cA) ^ ax[ma]) << 4));
      if constexpr (BNN) {
        const unsigned rowbyte = (unsigned)((ks * 16 + rnn) * 256);
#pragma unroll
        for (int np = 0; np < 2; np++)
          ldsm4t(bh[2 * np][0], bh[2 * np][1], bh[2 * np + 1][0], bh[2 * np + 1][1],
                 sB + rowbyte + bchunk[np]);
      } else {
#pragma unroll
        for (int np = 0; np < 2; np++)
          ldsm4(bh[2 * np][0], bh[2 * np][1], bh[2 * np + 1][0], bh[2 * np + 1][1],
                sB + boff[np] + (unsigned)(((kc0 + cB) ^ bx[np]) << 4));
      }
#pragma unroll
      for (int ma = 0; ma < 4; ma++)
#pragma unroll
        for (int na = 0; na < 4; na++) mma16(acc[ma][na], ah[ma], bh[na]);
    }
  }

  // ---- epilogue ----
  const int q = lane >> 2, t2 = lane & 3;
  if constexpr (CSKIP) __syncthreads();  // smax init visible
#pragma unroll
  for (int ma = 0; ma < 4; ma++) {
    float m0 = -3.0e38f, m1 = -3.0e38f;
#pragma unroll
    for (int na = 0; na < 4; na++) {
      const int row = r0 + wm + ma * 16 + q;
      const int col = c0 + wn + na * 8 + t2 * 2;
      float v0 = acc[ma][na][0], v1 = acc[ma][na][1];
      float v2 = acc[ma][na][2], v3 = acc[ma][na][3];
      if constexpr (EPI == 1) {
        __half* D = (__half*)Dv;
        float b0 = bias[col], b1 = bias[col + 1];
        *(__half2*)(D + (size_t)row * ldd + col) = __floats2half2_rn(v0 + b0, v1 + b1);
        *(__half2*)(D + (size_t)(row + 8) * ldd + col) = __floats2half2_rn(v2 + b0, v3 + b1);
      } else {
        float* D = (float*)Dv;
        v0 *= scale; v1 *= scale; v2 *= scale; v3 *= scale;
        *(float2*)(D + (size_t)row * ldd + col) = make_float2(v0, v1);
        *(float2*)(D + (size_t)(row + 8) * ldd + col) = make_float2(v2, v3);
        if constexpr (CSKIP) {
          m0 = fmaxf(m0, fmaxf(v0, v1));
          m1 = fmaxf(m1, fmaxf(v2, v3));
        }
      }
    }
    if constexpr (CSKIP) {
      m0 = fmaxf(m0, __shfl_xor_sync(0xffffffffu, m0, 1));
      m0 = fmaxf(m0, __shfl_xor_sync(0xffffffffu, m0, 2));
      m1 = fmaxf(m1, __shfl_xor_sync(0xffffffffu, m1, 1));
      m1 = fmaxf(m1, __shfl_xor_sync(0xffffffffu, m1, 2));
      if (t2 == 0) {
        atomicMax(&smax[wm + ma * 16 + q], fmap(m0));
        atomicMax(&smax[wm + ma * 16 + q + 8], fmap(m1));
      }
    }
  }
  if constexpr (CSKIP) {
    __syncthreads();
    if (tid < BM) atomicMax(&g_rowmax[r0 + tid], smax[tid]);
  }
}

// ---------------------------------------------------------------------------
// Prep kernels
// ---------------------------------------------------------------------------
__global__ __launch_bounds__(256) void conv_x(const float* __restrict__ in,
                                              __half* __restrict__ out, int n4) {
  int i = blockIdx.x * 256 + threadIdx.x;
  if (i < T_DIM) g_rowmax[i] = 0u;  // re-init row maxima every call
  if (i >= n4) return;
  float4 v = ((const float4*)in)[i];
  __half2* op = (__half2*)(out + (size_t)i * 4);
  op[0] = __floats2half2_rn(v.x, v.y);
  op[1] = __floats2half2_rn(v.z, v.w);
}

// W [C, N3] float -> W^T [N3, C] fp16
__global__ __launch_bounds__(256) void transpose_w(const float* __restrict__ W,
                                                   __half* __restrict__ oh) {
  __shared__ float t[32][33];
  const int bx = blockIdx.x * 32, by = blockIdx.y * 32;
  const int tx = threadIdx.x & 31, ty = threadIdx.x >> 5;
#pragma unroll
  for (int i = 0; i < 4; i++)
    t[ty + i * 8][tx] = W[(size_t)(by + ty + i * 8) * N3_DIM + bx + tx];
  __syncthreads();
#pragma unroll
  for (int i = 0; i < 4; i++) {
    float v = t[tx][ty + i * 8];
    oh[(size_t)(bx + ty + i * 8) * C_DIM + by + tx] = __float2half_rn(v);
  }
}

// ---------------------------------------------------------------------------
// Row softmax over [n_padd, row]; single S pass using precomputed row max
// (superset max — exactly cancelled by normalization). Writes P*2^14 fp16,
// bounded at the 128-aligned row-tile limit. Heavy rows first.
// ---------------------------------------------------------------------------
__global__ __launch_bounds__(256) void softmax_rows(const float* __restrict__ S,
                                                    __half* __restrict__ P,
                                                    const int* __restrict__ npad_p) {
  const int row = (int)gridDim.x - 1 - (int)blockIdx.x;  // longest rows first
  const int tid = threadIdx.x;
  const int npad = *npad_p;
  const float* rp = S + (size_t)row * T_DIM;
  __half* pp = P + (size_t)row * T_DIM;
  const int wend = ((row >> 7) + 1) << 7;  // GEMM3 read bound for this row
  __shared__ float red[8];
  if (row < npad) {
    for (int c = tid; c < wend; c += 256) pp[c] = __float2half(0.f);
    return;
  }
  const int lo = npad, hi = row;
  const float bmax = funmap(g_rowmax[row]);

  float ev[16];
  float s = 0.f;
#pragma unroll
  for (int i = 0; i < 16; i++) {
    int c = lo + tid + i * 256;
    float e = (c <= hi) ? __expf(rp[c] - bmax) * 16384.0f : 0.f;  // *2^14 exact
    ev[i] = e;
    s += e;
  }
#pragma unroll
  for (int o = 16; o > 0; o >>= 1) s += __shfl_xor_sync(0xffffffffu, s, o);
  if ((tid & 31) == 0) red[tid >> 5] = s;
  __syncthreads();
  float bsum = 0.f;
#pragma unroll
  for (int i = 0; i < 8; i++) bsum += red[i];
  const float inv = 16384.0f / bsum;  // final P = e/bsum * 2^14

  for (int c = tid; c < lo; c += 256) pp[c] = __float2half(0.f);
#pragma unroll
  for (int i = 0; i < 16; i++) {
    int c = lo + tid + i * 256;
    if (c <= hi) pp[c] = __float2half_rn(ev[i] * inv);
  }
  for (int c = hi + 1 + tid; c < wend; c += 256) pp[c] = __float2half(0.f);
}

extern "C" void kernel_launch(void* const* d_in, const int* in_sizes, int n_in,
                              void* d_out, int out_size) {
  const float* x = (const float*)d_in[0];
  const float* W = (const float*)d_in[1];
  const float* bias = (const float*)d_in[2];
  const int* n_padd = (const int*)d_in[3];
  float* y = (float*)d_out;

  __half *qkv, *P, *xh, *wth;
  float* S;
  cudaGetSymbolAddress((void**)&qkv, g_qkv);
  cudaGetSymbolAddress((void**)&S, g_S);
  cudaGetSymbolAddress((void**)&P, g_P);
  cudaGetSymbolAddress((void**)&xh, g_xh);
  cudaGetSymbolAddress((void**)&wth, g_wth);

  const float scale = 1.0f / sqrtf((float)NF_DIM);

  constexpr int SM_BYTES = NST * (BM * 128 + BN * 128);  // 98304 (2 CTAs/SM)

  cudaFuncSetAttribute((const void*)gemm_h<1, false, false, false>,
                       cudaFuncAttributeMaxDynamicSharedMemorySize, SM_BYTES);
  cudaFuncSetAttribute((const void*)gemm_h<0, true, false, false>,
                       cudaFuncAttributeMaxDynamicSharedMemorySize, SM_BYTES);
  cudaFuncSetAttribute((const void*)gemm_h<0, false, true, true>,
                       cudaFuncAttributeMaxDynamicSharedMemorySize, SM_BYTES);

  // Prep: x -> fp16 (+rowmax init) ; W -> W^T fp16
  conv_x<<<(T_DIM * C_DIM / 4 + 255) / 256, 256>>>(x, xh, T_DIM * C_DIM / 4);
  transpose_w<<<dim3(N3_DIM / 32, C_DIM / 32), 256>>>(W, wth);

  // GEMM1: qkv = x @ W + b   (NT; writes fp16)
  gemm_h<1, false, false, false><<<dim3(N3_DIM / BN, T_DIM / BM), NTHR, SM_BYTES>>>(
      (const uint16_t*)xh, (const uint16_t*)wth, qkv, bias, 0.f,
      C_DIM, C_DIM, C_DIM, N3_DIM);

  // GEMM2: S = (q @ k^T) * scale   (NT triangle, 528 CTAs; emits row maxima)
  gemm_h<0, true, false, false><<<528, NTHR, SM_BYTES>>>(
      (const uint16_t*)qkv, (const uint16_t*)(qkv + NF_DIM),
      S, nullptr, scale, NF_DIM, N3_DIM, N3_DIM, T_DIM);

  // Softmax -> P (fp16, *2^14, single pass using precomputed max)
  softmax_rows<<<T_DIM, 256>>>(S, P, n_padd);

  // GEMM3: y = P @ v * 2^-14   (A=P K-major; B=v NN direct from qkv)
  gemm_h<0, false, true, true><<<dim3(NF_DIM / BN, T_DIM / BM), NTHR, SM_BYTES>>>(
      (const uint16_t*)P, (const uint16_t*)(qkv + 2 * NF_DIM),
      y, nullptr, 6.103515625e-05f, T_DIM, T_DIM, N3_DIM, NF_DIM);
}

// round 15
// speedup vs baseline: 5.2342x; 1.0632x over previous
#include <cuda_runtime.h>
#include <cuda_fp16.h>
#include <math.h>
#include <cstdint>

#define T_DIM 4096
#define C_DIM 2048
#define NF_DIM 2048
#define N3_DIM 6144

constexpr int BM = 128, BN = 128, BK = 64;  // BK halves -> 128B smem rows (NT)
constexpr int NST = 3;                       // pipeline stages (32KB each)
constexpr int NTHR = 128;                    // 4 warps: 2(M) x 2(N) of 64x64

// Scratch (allocation-free rule: __device__ globals)
__device__ __half g_qkv[(size_t)T_DIM * N3_DIM];   // fp16 qkv (48 MB)
__device__ float g_S[(size_t)T_DIM * T_DIM];       // att logits (64 MB)
__device__ __half g_P[(size_t)T_DIM * T_DIM];      // P (fp16, *2^14)
__device__ __half g_xh[(size_t)T_DIM * C_DIM];     // x fp16
__device__ __half g_wth[(size_t)N3_DIM * C_DIM];   // W^T fp16
__device__ uint32_t g_rowmax[T_DIM];               // monotonic-uint row maxima

__device__ __forceinline__ uint32_t fmap(float f) {  // order-preserving f32->u32
  uint32_t u = __float_as_uint(f);
  return (u & 0x80000000u) ? ~u : (u | 0x80000000u);
}
__device__ __forceinline__ float funmap(uint32_t u) {
  return __uint_as_float((u & 0x80000000u) ? (u & 0x7FFFFFFFu) : ~u);
}

__device__ __forceinline__ void cpasync16(unsigned s, const void* g) {
  asm volatile("cp.async.cg.shared.global [%0], [%1], 16;\n" ::"r"(s), "l"(g));
}
__device__ __forceinline__ void cp_commit() { asm volatile("cp.async.commit_group;\n" ::); }
template <int N>
__device__ __forceinline__ void cp_wait() {
  asm volatile("cp.async.wait_group %0;\n" ::"n"(N));
}
__device__ __forceinline__ void ldsm4(uint32_t& r0, uint32_t& r1, uint32_t& r2,
                                      uint32_t& r3, unsigned addr) {
  asm volatile("ldmatrix.sync.aligned.m8n8.x4.shared.b16 {%0,%1,%2,%3}, [%4];"
               : "=r"(r0), "=r"(r1), "=r"(r2), "=r"(r3)
               : "r"(addr));
}
__device__ __forceinline__ void ldsm4t(uint32_t& r0, uint32_t& r1, uint32_t& r2,
                                       uint32_t& r3, unsigned addr) {
  asm volatile("ldmatrix.sync.aligned.m8n8.x4.trans.shared.b16 {%0,%1,%2,%3}, [%4];"
               : "=r"(r0), "=r"(r1), "=r"(r2), "=r"(r3)
               : "r"(addr));
}
__device__ __forceinline__ void mma16(float (&c)[4], const uint32_t (&a)[4],
                                      const uint32_t (&b)[2]) {
  asm volatile(
      "mma.sync.aligned.m16n8k16.row.col.f32.f16.f16.f32 "
      "{%0,%1,%2,%3}, {%4,%5,%6,%7}, {%8,%9}, {%0,%1,%2,%3};\n"
      : "+f"(c[0]), "+f"(c[1]), "+f"(c[2]), "+f"(c[3])
      : "r"(a[0]), "r"(a[1]), "r"(a[2]), "r"(a[3]), "r"(b[0]), "r"(b[1]));
}

// ---------------------------------------------------------------------------
// fp16 GEMM: D[M,N] = A[M,K] @ op(B)   (fp32 accum)
// CTA 128x128, 128 thr (4 warps of 64x64), 2 CTAs/SM, BK=64, 3-stage cp.async.
// A K-major. BNN=0: B[N,K] K-major (NT, ldmatrix). BNN=1: B[K,N] row-major
// (NN, ldmatrix.trans; tile = BK rows x 256B swizzled).
// EPI: 0 -> float out * scale ; 1 -> half out + bias
// CSKIP: compact causal-triangle 1D launch + row-max side output (GEMM2)
// CK:    causal K bound + heavy-first row order (GEMM3)
// ---------------------------------------------------------------------------
template <int EPI, bool CSKIP, bool CK, bool BNN>
__global__ __launch_bounds__(NTHR, 2) void gemm_h(
    const uint16_t* __restrict__ A, const uint16_t* __restrict__ B,
    void* __restrict__ Dv, const float* __restrict__ bias, float scale,
    int K, int lda, int ldb, int ldd) {
  constexpr int ATB = BM * 128;  // 16 KB A tile
  constexpr int BTB = BN * 128;  // 16 KB B tile (NT: 128x128B, NN: 64x256B)
  constexpr int STG = ATB + BTB;
  extern __shared__ __align__(16) char smem[];
  __shared__ uint32_t smax[BM];

  int r0, c0;
  if constexpr (CSKIP) {
    // triangular decode: row y has y+1 col-blocks; t = y(y+1)/2 + c
    int t = blockIdx.x;
    int y = (int)((sqrtf(8.f * (float)t + 1.f) - 1.f) * 0.5f);
    while ((y + 1) * (y + 2) / 2 <= t) y++;
    while (y * (y + 1) / 2 > t) y--;
    r0 = y * BM;
    c0 = (t - y * (y + 1) / 2) * BN;
  } else if constexpr (CK) {
    r0 = ((int)gridDim.y - 1 - (int)blockIdx.y) * BM;  // heavy rows first
    c0 = blockIdx.x * BN;
  } else {
    r0 = blockIdx.y * BM;
    c0 = blockIdx.x * BN;
  }
  const int kend = CK ? min(K, r0 + BM) : K;
  const int nk = kend / BK;

  const int tid = threadIdx.x, lane = tid & 31, warp = tid >> 5;
  const int wm = (warp >> 1) * 64, wn = (warp & 1) * 64;
  const unsigned sbase = (unsigned)__cvta_generic_to_shared(smem);

  if constexpr (CSKIP) smax[tid] = 0u;

  auto sw_off = [](int r, int c) {  // 128B-row XOR swizzle (A, B-NT)
    return (unsigned)(r * 128 + ((c ^ (r & 7)) << 4));
  };
  auto load_stage = [&](int s, int kt) {
    unsigned b = sbase + s * STG;
#pragma unroll
    for (int i = 0; i < 8; i++) {  // A: 128 rows x 8 chunks = 1024
      int id = tid + i * NTHR, r = id >> 3, c = id & 7;
      cpasync16(b + sw_off(r, c), A + (size_t)(r0 + r) * lda + kt + c * 8);
    }
    if constexpr (BNN) {
#pragma unroll
      for (int i = 0; i < 8; i++) {  // B: 64 rows x 16 chunks = 1024
        int id = tid + i * NTHR, r = id >> 4, c = id & 15;
        cpasync16(b + ATB + (unsigned)(r * 256 + ((c ^ (r & 7)) << 4)),
                  B + (size_t)(kt + r) * ldb + c0 + c * 8);
      }
    } else {
#pragma unroll
      for (int i = 0; i < 8; i++) {  // B: 128 rows x 8 chunks = 1024
        int id = tid + i * NTHR, r = id >> 3, c = id & 7;
        cpasync16(b + ATB + sw_off(r, c), B + (size_t)(c0 + r) * ldb + kt + c * 8);
      }
    }
    cp_commit();
  };

  float acc[4][8][4];
#pragma unroll
  for (int i = 0; i < 4; i++)
#pragma unroll
    for (int j = 0; j < 8; j++)
#pragma unroll
      for (int r = 0; r < 4; r++) acc[i][j][r] = 0.f;

#pragma unroll
  for (int s = 0; s < NST - 1; s++) load_stage(s, s * BK);

  // --- per-thread ldmatrix address components ---
  const int cA = lane >> 4;
  unsigned aoff[4];
  int ax[4];
#pragma unroll
  for (int ma = 0; ma < 4; ma++) {
    int rowA = wm + ma * 16 + (lane & 15);
    aoff[ma] = (unsigned)(rowA * 128);
    ax[ma] = rowA & 7;
  }
  // B-NT components (np covers 16 B-rows each, 4 per warp)
  const int cB = (lane >> 3) & 1;
  unsigned boff[4];
  int bx[4];
#pragma unroll
  for (int np = 0; np < 4; np++) {
    int rowB = wn + np * 16 + ((lane >> 4) * 8) + (lane & 7);
    boff[np] = (unsigned)(rowB * 128);
    bx[np] = rowB & 7;
  }
  // B-NN components: row = ks*16 + rnn ; chunk cb ^ (lane&7); 256B rows
  const int rnn = (lane & 7) + (((lane >> 3) & 1) << 3);
  unsigned bchunk[4];
#pragma unroll
  for (int np = 0; np < 4; np++) {
    int cb = (wn >> 3) + np * 2 + (lane >> 4);  // 0..15
    bchunk[np] = (unsigned)((cb ^ (lane & 7)) << 4);
  }

  for (int k = 0; k < nk; k++) {
    cp_wait<NST - 2>();
    __syncthreads();
    if (k + NST - 1 < nk) load_stage((k + NST - 1) % NST, (k + NST - 1) * BK);
    else cp_commit();  // keep group count consistent

    const unsigned sb = sbase + (unsigned)((k % NST) * STG);
    const unsigned sA = sb, sB = sb + ATB;

#pragma unroll
    for (int ks = 0; ks < 4; ks++) {
      const int kc0 = ks * 2;
      uint32_t ah[4][4], bh[8][2];
#pragma unroll
      for (int ma = 0; ma < 4; ma++)
        ldsm4(ah[ma][0], ah[ma][1], ah[ma][2], ah[ma][3],
              sA + aoff[ma] + (unsigned)(((kc0 + cA) ^ ax[ma]) << 4));
      if constexpr (BNN) {
        const unsigned rowbyte = (unsigned)((ks * 16 + rnn) * 256);
#pragma unroll
        for (int np = 0; np < 4; np++)
          ldsm4t(bh[2 * np][0], bh[2 * np][1], bh[2 * np + 1][0], bh[2 * np + 1][1],
                 sB + rowbyte + bchunk[np]);
      } else {
#pragma unroll
        for (int np = 0; np < 4; np++)
          ldsm4(bh[2 * np][0], bh[2 * np][1], bh[2 * np + 1][0], bh[2 * np + 1][1],
                sB + boff[np] + (unsigned)(((kc0 + cB) ^ bx[np]) << 4));
      }
#pragma unroll
      for (int ma = 0; ma < 4; ma++)
#pragma unroll
        for (int na = 0; na < 8; na++) mma16(acc[ma][na], ah[ma], bh[na]);
    }
  }

  // ---- epilogue ----
  const int q = lane >> 2, t2 = lane & 3;
  if constexpr (CSKIP) __syncthreads();  // smax init visible
#pragma unroll
  for (int ma = 0; ma < 4; ma++) {
    float m0 = -3.0e38f, m1 = -3.0e38f;
#pragma unroll
    for (int na = 0; na < 8; na++) {
      const int row = r0 + wm + ma * 16 + q;
      const int col = c0 + wn + na * 8 + t2 * 2;
      float v0 = acc[ma][na][0], v1 = acc[ma][na][1];
      float v2 = acc[ma][na][2], v3 = acc[ma][na][3];
      if constexpr (EPI == 1) {
        __half* D = (__half*)Dv;
        float b0 = bias[col], b1 = bias[col + 1];
        *(__half2*)(D + (size_t)row * ldd + col) = __floats2half2_rn(v0 + b0, v1 + b1);
        *(__half2*)(D + (size_t)(row + 8) * ldd + col) = __floats2half2_rn(v2 + b0, v3 + b1);
      } else {
        float* D = (float*)Dv;
        v0 *= scale; v1 *= scale; v2 *= scale; v3 *= scale;
        *(float2*)(D + (size_t)row * ldd + col) = make_float2(v0, v1);
        *(float2*)(D + (size_t)(row + 8) * ldd + col) = make_float2(v2, v3);
        if constexpr (CSKIP) {
          m0 = fmaxf(m0, fmaxf(v0, v1));
          m1 = fmaxf(m1, fmaxf(v2, v3));
        }
      }
    }
    if constexpr (CSKIP) {
      m0 = fmaxf(m0, __shfl_xor_sync(0xffffffffu, m0, 1));
      m0 = fmaxf(m0, __shfl_xor_sync(0xffffffffu, m0, 2));
      m1 = fmaxf(m1, __shfl_xor_sync(0xffffffffu, m1, 1));
      m1 = fmaxf(m1, __shfl_xor_sync(0xffffffffu, m1, 2));
      if (t2 == 0) {
        atomicMax(&smax[wm + ma * 16 + q], fmap(m0));
        atomicMax(&smax[wm + ma * 16 + q + 8], fmap(m1));
      }
    }
  }
  if constexpr (CSKIP) {
    __syncthreads();
    atomicMax(&g_rowmax[r0 + tid], smax[tid]);
  }
}

// ---------------------------------------------------------------------------
// Prep kernels
// ---------------------------------------------------------------------------
__global__ __launch_bounds__(256) void conv_x(const float* __restrict__ in,
                                              __half* __restrict__ out, int n4) {
  int i = blockIdx.x * 256 + threadIdx.x;
  if (i < T_DIM) g_rowmax[i] = 0u;  // re-init row maxima every call
  if (i >= n4) return;
  float4 v = ((const float4*)in)[i];
  __half2* op = (__half2*)(out + (size_t)i * 4);
  op[0] = __floats2half2_rn(v.x, v.y);
  op[1] = __floats2half2_rn(v.z, v.w);
}

// W [C, N3] float -> W^T [N3, C] fp16
__global__ __launch_bounds__(256) void transpose_w(const float* __restrict__ W,
                                                   __half* __restrict__ oh) {
  __shared__ float t[32][33];
  const int bx = blockIdx.x * 32, by = blockIdx.y * 32;
  const int tx = threadIdx.x & 31, ty = threadIdx.x >> 5;
#pragma unroll
  for (int i = 0; i < 4; i++)
    t[ty + i * 8][tx] = W[(size_t)(by + ty + i * 8) * N3_DIM + bx + tx];
  __syncthreads();
#pragma unroll
  for (int i = 0; i < 4; i++) {
    float v = t[tx][ty + i * 8];
    oh[(size_t)(bx + ty + i * 8) * C_DIM + by + tx] = __float2half_rn(v);
  }
}

// ---------------------------------------------------------------------------
// Row softmax over [n_padd, row]; single S pass using precomputed row max.
// Vectorized: float4 S reads, uint2 (4xhalf) P writes. Writes bounded at the
// 128-aligned row-tile limit. Heavy rows first.
// ---------------------------------------------------------------------------
__global__ __launch_bounds__(256) void softmax_rows(const float* __restrict__ S,
                                                    __half* __restrict__ P,
                                                    const int* __restrict__ npad_p) {
  const int row = (int)gridDim.x - 1 - (int)blockIdx.x;  // longest rows first
  const int tid = threadIdx.x;
  const int npad = *npad_p;
  const float* rp = S + (size_t)row * T_DIM;
  __half* pp = P + (size_t)row * T_DIM;
  const int wend = ((row >> 7) + 1) << 7;  // GEMM3 read bound for this row
  __shared__ float red[8];
  if (row < npad) {
    for (int c = tid * 4; c < wend; c += 1024)
      *(uint2*)(pp + c) = make_uint2(0u, 0u);
    return;
  }
  const int lo = npad, hi = row;
  const float bmax = funmap(g_rowmax[row]);
  const int start = lo & ~3;

  float ev[16];
  float s = 0.f;
#pragma unroll
  for (int i = 0; i < 4; i++) {
    int c = start + (tid + i * 256) * 4;
    if (c <= hi) {
      float4 v = *(const float4*)(rp + c);
      float e0 = (c >= lo) ? __expf(v.x - bmax) * 16384.0f : 0.f;
      float e1 = (c + 1 >= lo && c + 1 <= hi) ? __expf(v.y - bmax) * 16384.0f : 0.f;
      float e2 = (c + 2 >= lo && c + 2 <= hi) ? __expf(v.z - bmax) * 16384.0f : 0.f;
      float e3 = (c + 3 >= lo && c + 3 <= hi) ? __expf(v.w - bmax) * 16384.0f : 0.f;
      ev[i * 4 + 0] = e0; ev[i * 4 + 1] = e1; ev[i * 4 + 2] = e2; ev[i * 4 + 3] = e3;
      s += (e0 + e1) + (e2 + e3);
    } else {
      ev[i * 4 + 0] = ev[i * 4 + 1] = ev[i * 4 + 2] = ev[i * 4 + 3] = 0.f;
    }
  }
#pragma unroll
  for (int o = 16; o > 0; o >>= 1) s += __shfl_xor_sync(0xffffffffu, s, o);
  if ((tid & 31) == 0) red[tid >> 5] = s;
  __syncthreads();
  float bsum = 0.f;
#pragma unroll
  for (int i = 0; i < 8; i++) bsum += red[i];
  const float inv = 16384.0f / bsum;  // final P = e/bsum * 2^14

  // zero [0, start) vectorized (start is 4-aligned)
  for (int c = tid * 4; c < start; c += 1024) *(uint2*)(pp + c) = make_uint2(0u, 0u);
  // main window [start, hi] vectorized (ev holds zeros outside [lo,hi])
#pragma unroll
  for (int i = 0; i < 4; i++) {
    int c = start + (tid + i * 256) * 4;
    if (c <= hi) {
      __half2 h0 = __floats2half2_rn(ev[i * 4 + 0] * inv, ev[i * 4 + 1] * inv);
      __half2 h1 = __floats2half2_rn(ev[i * 4 + 2] * inv, ev[i * 4 + 3] * inv);
      uint2 u;
      u.x = *(uint32_t*)&h0;
      u.y = *(uint32_t*)&h1;
      *(uint2*)(pp + c) = u;
    }
  }
  // zero (hi, wend): start at first 4-aligned c > hi; scalar-fill the gap
  const int tail = (hi + 4) & ~3;
  for (int c = hi + 1 + tid; c < tail && c < wend; c += 256) pp[c] = __float2half(0.f);
  for (int c = tail + tid * 4; c < wend; c += 1024) *(uint2*)(pp + c) = make_uint2(0u, 0u);
}

extern "C" void kernel_launch(void* const* d_in, const int* in_sizes, int n_in,
                              void* d_out, int out_size) {
  const float* x = (const float*)d_in[0];
  const float* W = (const float*)d_in[1];
  const float* bias = (const float*)d_in[2];
  const int* n_padd = (const int*)d_in[3];
  float* y = (float*)d_out;

  __half *qkv, *P, *xh, *wth;
  float* S;
  cudaGetSymbolAddress((void**)&qkv, g_qkv);
  cudaGetSymbolAddress((void**)&S, g_S);
  cudaGetSymbolAddress((void**)&P, g_P);
  cudaGetSymbolAddress((void**)&xh, g_xh);
  cudaGetSymbolAddress((void**)&wth, g_wth);

  const float scale = 1.0f / sqrtf((float)NF_DIM);

  constexpr int SM_BYTES = NST * (BM * 128 + BN * 128);  // 98304 (2 CTAs/SM)

  cudaFuncSetAttribute((const void*)gemm_h<1, false, false, false>,
                       cudaFuncAttributeMaxDynamicSharedMemorySize, SM_BYTES);
  cudaFuncSetAttribute((const void*)gemm_h<0, true, false, false>,
                       cudaFuncAttributeMaxDynamicSharedMemorySize, SM_BYTES);
  cudaFuncSetAttribute((const void*)gemm_h<0, false, true, true>,
                       cudaFuncAttributeMaxDynamicSharedMemorySize, SM_BYTES);

  // Prep: x -> fp16 (+rowmax init) ; W -> W^T fp16
  conv_x<<<(T_DIM * C_DIM / 4 + 255) / 256, 256>>>(x, xh, T_DIM * C_DIM / 4);
  transpose_w<<<dim3(N3_DIM / 32, C_DIM / 32), 256>>>(W, wth);

  // GEMM1: qkv = x @ W + b   (NT; writes fp16)
  gemm_h<1, false, false, false><<<dim3(N3_DIM / BN, T_DIM / BM), NTHR, SM_BYTES>>>(
      (const uint16_t*)xh, (const uint16_t*)wth, qkv, bias, 0.f,
      C_DIM, C_DIM, C_DIM, N3_DIM);

  // GEMM2: S = (q @ k^T) * scale   (NT triangle, 528 CTAs; emits row maxima)
  gemm_h<0, true, false, false><<<528, NTHR, SM_BYTES>>>(
      (const uint16_t*)qkv, (const uint16_t*)(qkv + NF_DIM),
      S, nullptr, scale, NF_DIM, N3_DIM, N3_DIM, T_DIM);

  // Softmax -> P (fp16, *2^14, single vectorized pass using precomputed max)
  softmax_rows<<<T_DIM, 256>>>(S, P, n_padd);

  // GEMM3: y = P @ v * 2^-14   (A=P K-major; B=v NN direct from qkv)
  gemm_h<0, false, true, true><<<dim3(NF_DIM / BN, T_DIM / BM), NTHR, SM_BYTES>>>(
      (const uint16_t*)P, (const uint16_t*)(qkv + 2 * NF_DIM),
      y, nullptr, 6.103515625e-05f, T_DIM, T_DIM, N3_DIM, NF_DIM);
}